// round 1
// baseline (speedup 1.0000x reference)
#include <cuda_runtime.h>
#include <math.h>

#define TOKS 131072          // 2048 windows * 64 tokens
#define CDIM 384

// Scratch (static device arrays; aliased across phases):
//   g_bufA: Y (post-LN1), later O (attention out)
//   g_bufB: WIN (windowed x), later H (win + attn proj)  [in-place alias safe: 1:1 elementwise]
//   g_bufC: QKV, later Y2 (first TOKS*384) + G (next TOKS*768)
__device__ float g_bufA[(size_t)TOKS * 384];
__device__ float g_bufB[(size_t)TOKS * 384];
__device__ float g_bufC[(size_t)TOKS * 1152];

// ---------------------------------------------------------------------------
// Kernel 1: window gather + LayerNorm1.  One block handles 16 tokens (2 window
// rows) of one window. Stages x into smem transposed so both the gather from
// NCHW x and the row-major writes of Y/WIN are coalesced.
// grid = 2048*4 blocks, 256 threads.
// ---------------------------------------------------------------------------
__global__ void __launch_bounds__(256) ln1_gather_kernel(
    const float* __restrict__ x,
    const float* __restrict__ gw, const float* __restrict__ gb,
    float* __restrict__ Y, float* __restrict__ WIN)
{
    __shared__ float tile[384][17];
    __shared__ float s_mu[16], s_rs[16];

    int blk  = blockIdx.x;
    int win  = blk >> 2;
    int part = blk & 3;                 // which 16 spatial positions
    int b  = win >> 8;
    int wh = (win >> 4) & 15;
    int ww = win & 15;

    int tid = threadIdx.x;
    int sl  = tid & 15;                 // local spatial 0..15
    int s   = part * 16 + sl;           // spatial within window 0..63
    int r   = s >> 3, cw = s & 7;
    long xbase = (long)b * 384 * 16384 + (long)(wh * 8 + r) * 128 + ww * 8 + cw;

    // gather: threads tid>>4 cover channels, strided
    for (int c = tid >> 4; c < 384; c += 16)
        tile[c][sl] = x[xbase + (long)c * 16384];
    __syncthreads();

    // stats: 8 warps x 2 tokens each
    int lane = tid & 31, wd = tid >> 5;
    for (int t = wd * 2; t < wd * 2 + 2; t++) {
        float sum = 0.f, sq = 0.f;
        for (int c = lane; c < 384; c += 32) {
            float v = tile[c][t];
            sum += v; sq += v * v;
        }
        #pragma unroll
        for (int o = 16; o; o >>= 1) {
            sum += __shfl_xor_sync(~0u, sum, o);
            sq  += __shfl_xor_sync(~0u, sq,  o);
        }
        if (lane == 0) {
            float m = sum * (1.f / 384.f);
            float var = sq * (1.f / 384.f) - m * m;
            s_mu[t] = m;
            s_rs[t] = rsqrtf(var + 1e-5f);
        }
    }
    __syncthreads();

    long tok0 = (long)win * 64 + part * 16;
    for (int idx = tid; idx < 16 * 384; idx += 256) {
        int c = idx % 384, t = idx / 384;
        float v = tile[c][t];
        long o = (tok0 + t) * 384 + c;
        WIN[o] = v;
        Y[o] = (v - s_mu[t]) * s_rs[t] * gw[c] + gb[c];
    }
}

// ---------------------------------------------------------------------------
// Tiled SGEMM: OUT[M,N] = A[M,K] @ W[N,K]^T + bias, with epilogue modes.
// BM=128, BN=64, BK=16, 256 threads, 8x4 microtile.
//  MODE 0: + bias                       (QKV)
//  MODE 1: + bias, exact gelu           (MLP1)
//  MODE 2: + bias + res                 (attn out proj -> H)
//  MODE 3: + bias + res, window-reverse scatter to NCHW output (MLP2)
// ---------------------------------------------------------------------------
template<int MODE>
__global__ void __launch_bounds__(256) gemm_kernel(
    const float* __restrict__ A, const float* __restrict__ W,
    const float* __restrict__ bias, const float* __restrict__ res,
    float* __restrict__ out, int K, int N)
{
    __shared__ float As[16][132];
    __shared__ float Ws[16][68];

    int  n0 = blockIdx.x * 64;
    long m0 = (long)blockIdx.y * 128;
    int tid = threadIdx.x;
    int tn = tid & 15, tm = tid >> 4;

    float acc[8][4] = {};

    for (int k0 = 0; k0 < K; k0 += 16) {
        // A tile 128x16: 2 float4 per thread, stored transposed
        #pragma unroll
        for (int i = 0; i < 2; i++) {
            int idx = tid + i * 256;
            int row = idx >> 2;
            int kc  = (idx & 3) * 4;
            float4 a4 = *(const float4*)&A[(m0 + row) * K + k0 + kc];
            As[kc + 0][row] = a4.x; As[kc + 1][row] = a4.y;
            As[kc + 2][row] = a4.z; As[kc + 3][row] = a4.w;
        }
        // W tile 64x16: 1 float4 per thread, stored transposed
        {
            int row = tid >> 2;
            int kc  = (tid & 3) * 4;
            float4 w4 = *(const float4*)&W[(long)(n0 + row) * K + k0 + kc];
            Ws[kc + 0][row] = w4.x; Ws[kc + 1][row] = w4.y;
            Ws[kc + 2][row] = w4.z; Ws[kc + 3][row] = w4.w;
        }
        __syncthreads();

        #pragma unroll
        for (int kk = 0; kk < 16; kk++) {
            float4 a0 = *(const float4*)&As[kk][tm * 8];
            float4 a1 = *(const float4*)&As[kk][tm * 8 + 4];
            float4 w0 = *(const float4*)&Ws[kk][tn * 4];
            float a[8] = {a0.x, a0.y, a0.z, a0.w, a1.x, a1.y, a1.z, a1.w};
            float w[4] = {w0.x, w0.y, w0.z, w0.w};
            #pragma unroll
            for (int i = 0; i < 8; i++)
                #pragma unroll
                for (int j = 0; j < 4; j++)
                    acc[i][j] += a[i] * w[j];
        }
        __syncthreads();
    }

    float4 b4 = *(const float4*)&bias[n0 + tn * 4];
    float bv[4] = {b4.x, b4.y, b4.z, b4.w};

    if (MODE == 3) {
        // token run m..m+7 is one full window row (8 consecutive w)
        long m = m0 + tm * 8;
        int win = (int)(m >> 6);
        int s   = (int)(m & 63);
        int b   = win >> 8, wh = (win >> 4) & 15, ww = win & 15;
        int r   = s >> 3;
        int h   = wh * 8 + r;
        int w0p = ww * 8;
        float rs[8][4];
        #pragma unroll
        for (int i = 0; i < 8; i++) {
            float4 r4 = *(const float4*)&res[(m + i) * 384 + n0 + tn * 4];
            rs[i][0] = r4.x; rs[i][1] = r4.y; rs[i][2] = r4.z; rs[i][3] = r4.w;
        }
        #pragma unroll
        for (int j = 0; j < 4; j++) {
            int n = n0 + tn * 4 + j;
            long base = (((long)b * 384 + n) * 128 + h) * 128 + w0p;
            float v[8];
            #pragma unroll
            for (int i = 0; i < 8; i++) v[i] = acc[i][j] + bv[j] + rs[i][j];
            *(float4*)&out[base]     = make_float4(v[0], v[1], v[2], v[3]);
            *(float4*)&out[base + 4] = make_float4(v[4], v[5], v[6], v[7]);
        }
    } else {
        #pragma unroll
        for (int i = 0; i < 8; i++) {
            long m = m0 + tm * 8 + i;
            float v[4];
            #pragma unroll
            for (int j = 0; j < 4; j++) {
                v[j] = acc[i][j] + bv[j];
                if (MODE == 1) {
                    float xv = v[j];
                    v[j] = 0.5f * xv * (1.f + erff(xv * 0.70710678118654752f));
                }
            }
            if (MODE == 2) {
                float4 r4 = *(const float4*)&res[m * N + n0 + tn * 4];
                v[0] += r4.x; v[1] += r4.y; v[2] += r4.z; v[3] += r4.w;
            }
            *(float4*)&out[m * N + n0 + tn * 4] = make_float4(v[0], v[1], v[2], v[3]);
        }
    }
}

// ---------------------------------------------------------------------------
// Kernel 3: attention per (window, head). S=64, hd=48.
// grid = (8, 2048), 256 threads. q/k in smem -> scores -> softmax -> P@V
// (v reuses q's smem buffer).
// ---------------------------------------------------------------------------
__global__ void __launch_bounds__(256) attn_kernel(
    const float* __restrict__ QKV, float* __restrict__ O)
{
    __shared__ float qv[64][49];   // q, later v
    __shared__ float ks[64][49];
    __shared__ float p[64][65];

    int head = blockIdx.x;
    long tok0 = (long)blockIdx.y * 64;
    int tid = threadIdx.x;
    int qo = head * 48, ko = 384 + head * 48, vo = 768 + head * 48;

    for (int idx = tid; idx < 64 * 48; idx += 256) {
        int s = idx / 48, f = idx % 48;
        const float* row = QKV + (tok0 + s) * 1152;
        qv[s][f] = row[qo + f];
        ks[s][f] = row[ko + f];
    }
    __syncthreads();

    int i0 = (tid >> 4) * 4;
    int j0 = (tid & 15) * 4;
    {
        float acc[4][4] = {};
        #pragma unroll 4
        for (int d = 0; d < 48; d++) {
            float a[4], bvv[4];
            #pragma unroll
            for (int ii = 0; ii < 4; ii++) a[ii] = qv[i0 + ii][d];
            #pragma unroll
            for (int jj = 0; jj < 4; jj++) bvv[jj] = ks[j0 + jj][d];
            #pragma unroll
            for (int ii = 0; ii < 4; ii++)
                #pragma unroll
                for (int jj = 0; jj < 4; jj++)
                    acc[ii][jj] += a[ii] * bvv[jj];
        }
        const float scale = 0.14433756729740645f;   // 1/sqrt(48)
        #pragma unroll
        for (int ii = 0; ii < 4; ii++)
            #pragma unroll
            for (int jj = 0; jj < 4; jj++)
                p[i0 + ii][j0 + jj] = acc[ii][jj] * scale;
    }
    __syncthreads();

    // overwrite qv with V (independent of softmax on p)
    for (int idx = tid; idx < 64 * 48; idx += 256) {
        int s = idx / 48, f = idx % 48;
        qv[s][f] = QKV[(tok0 + s) * 1152 + vo + f];
    }

    // softmax: 8 warps x 8 rows
    int lane = tid & 31, wd = tid >> 5;
    for (int t = wd * 8; t < wd * 8 + 8; t++) {
        float v0 = p[t][lane], v1 = p[t][lane + 32];
        float mx = fmaxf(v0, v1);
        #pragma unroll
        for (int o = 16; o; o >>= 1) mx = fmaxf(mx, __shfl_xor_sync(~0u, mx, o));
        float e0 = __expf(v0 - mx), e1 = __expf(v1 - mx);
        float sm = e0 + e1;
        #pragma unroll
        for (int o = 16; o; o >>= 1) sm += __shfl_xor_sync(~0u, sm, o);
        float inv = 1.f / sm;
        p[t][lane] = e0 * inv;
        p[t][lane + 32] = e1 * inv;
    }
    __syncthreads();

    // O = P @ V : microtile 4 rows x 3 cols
    int f0 = (tid & 15) * 3;
    float oc[4][3] = {};
    #pragma unroll 4
    for (int j = 0; j < 64; j++) {
        float a[4], bvv[3];
        #pragma unroll
        for (int ii = 0; ii < 4; ii++) a[ii] = p[i0 + ii][j];
        #pragma unroll
        for (int ff = 0; ff < 3; ff++) bvv[ff] = qv[j][f0 + ff];
        #pragma unroll
        for (int ii = 0; ii < 4; ii++)
            #pragma unroll
            for (int ff = 0; ff < 3; ff++)
                oc[ii][ff] += a[ii] * bvv[ff];
    }
    #pragma unroll
    for (int ii = 0; ii < 4; ii++)
        #pragma unroll
        for (int ff = 0; ff < 3; ff++)
            O[(tok0 + i0 + ii) * 384 + head * 48 + f0 + ff] = oc[ii][ff];
}

// ---------------------------------------------------------------------------
// Kernel 5: LayerNorm2. One block per token (128 threads, 3 elems each).
// ---------------------------------------------------------------------------
__global__ void __launch_bounds__(128) ln2_kernel(
    const float* __restrict__ Hh,
    const float* __restrict__ gw, const float* __restrict__ gb,
    float* __restrict__ Y2)
{
    long t = blockIdx.x;
    int tid = threadIdx.x;
    const float* row = Hh + t * 384;
    float v[3];
    float sum = 0.f, sq = 0.f;
    #pragma unroll
    for (int i = 0; i < 3; i++) {
        v[i] = row[tid + i * 128];
        sum += v[i]; sq += v[i] * v[i];
    }
    __shared__ float ssum[4], ssq[4];
    #pragma unroll
    for (int o = 16; o; o >>= 1) {
        sum += __shfl_xor_sync(~0u, sum, o);
        sq  += __shfl_xor_sync(~0u, sq,  o);
    }
    if ((tid & 31) == 0) { ssum[tid >> 5] = sum; ssq[tid >> 5] = sq; }
    __syncthreads();
    sum = ssum[0] + ssum[1] + ssum[2] + ssum[3];
    sq  = ssq[0]  + ssq[1]  + ssq[2]  + ssq[3];
    float m  = sum * (1.f / 384.f);
    float rs = rsqrtf(sq * (1.f / 384.f) - m * m + 1e-5f);
    #pragma unroll
    for (int i = 0; i < 3; i++) {
        int c = tid + i * 128;
        Y2[t * 384 + c] = (v[i] - m) * rs * gw[c] + gb[c];
    }
}

// ---------------------------------------------------------------------------
extern "C" void kernel_launch(void* const* d_in, const int* in_sizes, int n_in,
                              void* d_out, int out_size)
{
    const float* x     = (const float*)d_in[0];
    const float* n1_w  = (const float*)d_in[1];
    const float* n1_b  = (const float*)d_in[2];
    const float* in_w  = (const float*)d_in[3];
    const float* in_b  = (const float*)d_in[4];
    const float* out_w = (const float*)d_in[5];
    const float* out_b = (const float*)d_in[6];
    const float* n2_w  = (const float*)d_in[7];
    const float* n2_b  = (const float*)d_in[8];
    const float* w1    = (const float*)d_in[9];
    const float* b1    = (const float*)d_in[10];
    const float* w2    = (const float*)d_in[11];
    const float* b2    = (const float*)d_in[12];
    float* out = (float*)d_out;

    float *Y, *WIN, *QKV;
    cudaGetSymbolAddress((void**)&Y,   g_bufA);
    cudaGetSymbolAddress((void**)&WIN, g_bufB);
    cudaGetSymbolAddress((void**)&QKV, g_bufC);
    float* O  = Y;                       // g_bufA reused
    float* H  = WIN;                     // g_bufB reused (elementwise 1:1 alias)
    float* Y2 = QKV;                     // g_bufC front
    float* G  = QKV + (size_t)TOKS * 384;// g_bufC back

    // 1. gather + LN1
    ln1_gather_kernel<<<2048 * 4, 256>>>(x, n1_w, n1_b, Y, WIN);
    // 2. QKV projection
    gemm_kernel<0><<<dim3(1152 / 64, TOKS / 128), 256>>>(Y, in_w, in_b, nullptr, QKV, 384, 1152);
    // 3. attention
    attn_kernel<<<dim3(8, 2048), 256>>>(QKV, O);
    // 4. out projection + residual -> H
    gemm_kernel<2><<<dim3(384 / 64, TOKS / 128), 256>>>(O, out_w, out_b, WIN, H, 384, 384);
    // 5. LN2
    ln2_kernel<<<TOKS, 128>>>(H, n2_w, n2_b, Y2);
    // 6. MLP fc1 + gelu
    gemm_kernel<1><<<dim3(768 / 64, TOKS / 128), 256>>>(Y2, w1, b1, nullptr, G, 384, 768);
    // 7. MLP fc2 + residual + window-reverse scatter
    gemm_kernel<3><<<dim3(384 / 64, TOKS / 128), 256>>>(G, w2, b2, H, out, 768, 384);
}

// round 3
// speedup vs baseline: 2.3549x; 2.3549x over previous
#include <cuda_runtime.h>
#include <math.h>
#include <stdint.h>

#define TOKS 131072          // 2048 windows * 64 tokens

// Scratch (static device arrays; aliased across phases):
__device__ float g_bufA[(size_t)TOKS * 384];   // Y, later O
__device__ float g_bufB[(size_t)TOKS * 384];   // WIN, later H
__device__ float g_bufC[(size_t)TOKS * 1152];  // QKV, later Y2 + G

// ===========================================================================
// cp.async + mma.sync tf32 helpers (portable PTX, no 'a'-target features)
// ===========================================================================
__device__ __forceinline__ void cp16(uint32_t dst, const void* src) {
    asm volatile("cp.async.cg.shared.global [%0], [%1], 16;"
        :: "r"(dst), "l"(src));
}
__device__ __forceinline__ void mma8(float* d, const uint32_t* a, const uint32_t* b) {
    asm volatile(
        "mma.sync.aligned.m16n8k8.row.col.f32.tf32.tf32.f32 "
        "{%0,%1,%2,%3}, {%4,%5,%6,%7}, {%8,%9}, {%0,%1,%2,%3};"
        : "+f"(d[0]), "+f"(d[1]), "+f"(d[2]), "+f"(d[3])
        : "r"(a[0]), "r"(a[1]), "r"(a[2]), "r"(a[3]), "r"(b[0]), "r"(b[1]));
}

// ===========================================================================
// Kernel 1: window gather + LayerNorm1
// ===========================================================================
__global__ void __launch_bounds__(256) ln1_gather_kernel(
    const float* __restrict__ x,
    const float* __restrict__ gw, const float* __restrict__ gb,
    float* __restrict__ Y, float* __restrict__ WIN)
{
    __shared__ float tile[384][17];
    __shared__ float s_mu[16], s_rs[16];

    int blk  = blockIdx.x;
    int win  = blk >> 2;
    int part = blk & 3;
    int b  = win >> 8;
    int wh = (win >> 4) & 15;
    int ww = win & 15;

    int tid = threadIdx.x;
    int sl  = tid & 15;
    int s   = part * 16 + sl;
    int r   = s >> 3, cw = s & 7;
    long xbase = (long)b * 384 * 16384 + (long)(wh * 8 + r) * 128 + ww * 8 + cw;

    for (int c = tid >> 4; c < 384; c += 16)
        tile[c][sl] = x[xbase + (long)c * 16384];
    __syncthreads();

    int lane = tid & 31, wd = tid >> 5;
    for (int t = wd * 2; t < wd * 2 + 2; t++) {
        float sum = 0.f, sq = 0.f;
        for (int c = lane; c < 384; c += 32) {
            float v = tile[c][t];
            sum += v; sq += v * v;
        }
        #pragma unroll
        for (int o = 16; o; o >>= 1) {
            sum += __shfl_xor_sync(~0u, sum, o);
            sq  += __shfl_xor_sync(~0u, sq,  o);
        }
        if (lane == 0) {
            float m = sum * (1.f / 384.f);
            float var = sq * (1.f / 384.f) - m * m;
            s_mu[t] = m;
            s_rs[t] = rsqrtf(var + 1e-5f);
        }
    }
    __syncthreads();

    long tok0 = (long)win * 64 + part * 16;
    for (int idx = tid; idx < 16 * 384; idx += 256) {
        int c = idx % 384, t = idx / 384;
        float v = tile[c][t];
        long o = (tok0 + t) * 384 + c;
        WIN[o] = v;
        Y[o] = (v - s_mu[t]) * s_rs[t] * gw[c] + gb[c];
    }
}

// ===========================================================================
// TF32 tensor-core GEMM: OUT[M,N] = A[M,K] @ W[N,K]^T + bias (+epilogues)
// BM=128, BN=128, BK=16, double-buffered cp.async, 256 threads (8 warps).
// Warp grid 2(M)x4(N); each warp: 4 m16 x 4 n8 mma tiles, k8 x2 per stage.
//  MODE 0: + bias                       (QKV)
//  MODE 1: + bias, exact gelu           (MLP1)
//  MODE 2: + bias + res                 (attn out proj -> H)
//  MODE 3: + bias + res, window-reverse scatter to NCHW out (MLP2)
// Smem: 2 stages x (A 128x20f + B 128x20f) = 40960B; MODE3 reuses it as
// a 128x66f transpose buffer for coalesced NCHW stores.
// ===========================================================================
template<int MODE>
__global__ void __launch_bounds__(256, 2) mma_gemm(
    const float* __restrict__ A, const float* __restrict__ W,
    const float* __restrict__ bias, const float* __restrict__ res,
    float* __restrict__ out, int K, int N)
{
    __shared__ float sm[10240];   // 40960 bytes

    const int tid  = threadIdx.x;
    const int lane = tid & 31, wid = tid >> 5;
    const int wm = wid & 1;       // M half (64 rows)
    const int wn = wid >> 1;      // N quarter (32 cols)
    const int gr = lane >> 2;     // group row 0..7
    const int cg = lane & 3;      // col-in-group 0..3

    const long m0 = (long)blockIdx.y * 128;
    const int  n0 = blockIdx.x * 128;

    const uint32_t sb = (uint32_t)__cvta_generic_to_shared(sm);
    const float* Ag = A + m0 * K;
    const float* Wg = W + (long)n0 * K;

    float acc[4][4][4];
    #pragma unroll
    for (int i = 0; i < 4; i++)
        #pragma unroll
        for (int j = 0; j < 4; j++)
            #pragma unroll
            for (int k = 0; k < 4; k++) acc[i][j][k] = 0.f;

    const int NS = K >> 4;

    // stage issue: 128 rows x 16 floats per tile, 4 float4 rows, 2 per thread
    auto issue = [&](int s, int p) {
        #pragma unroll
        for (int i = 0; i < 2; i++) {
            int idx = tid + i * 256;
            int row = idx >> 2, c4 = idx & 3;
            cp16(sb + (p * 5120 + row * 20 + c4 * 4) * 4,
                 Ag + (long)row * K + s * 16 + c4 * 4);
            cp16(sb + (p * 5120 + 2560 + row * 20 + c4 * 4) * 4,
                 Wg + (long)row * K + s * 16 + c4 * 4);
        }
        asm volatile("cp.async.commit_group;");
    };

    issue(0, 0);
    for (int s = 0; s < NS; s++) {
        int p = s & 1;
        if (s + 1 < NS) {
            issue(s + 1, p ^ 1);
            asm volatile("cp.async.wait_group 1;");
        } else {
            asm volatile("cp.async.wait_group 0;");
        }
        __syncthreads();

        const float* As = sm + p * 5120;
        const float* Bs = As + 2560;

        #pragma unroll
        for (int kk = 0; kk < 2; kk++) {
            uint32_t af[4][4], bf[4][2];
            #pragma unroll
            for (int mt = 0; mt < 4; mt++) {
                int r = wm * 64 + mt * 16 + gr;
                int c = kk * 8 + cg;
                af[mt][0] = __float_as_uint(As[r * 20 + c]);
                af[mt][1] = __float_as_uint(As[(r + 8) * 20 + c]);
                af[mt][2] = __float_as_uint(As[r * 20 + c + 4]);
                af[mt][3] = __float_as_uint(As[(r + 8) * 20 + c + 4]);
            }
            #pragma unroll
            for (int nt = 0; nt < 4; nt++) {
                int rn = wn * 32 + nt * 8 + gr;
                int c  = kk * 8 + cg;
                bf[nt][0] = __float_as_uint(Bs[rn * 20 + c]);
                bf[nt][1] = __float_as_uint(Bs[rn * 20 + c + 4]);
            }
            #pragma unroll
            for (int mt = 0; mt < 4; mt++)
                #pragma unroll
                for (int nt = 0; nt < 4; nt++)
                    mma8(acc[mt][nt], af[mt], bf[nt]);
        }
        __syncthreads();
    }

    if (MODE != 3) {
        #pragma unroll
        for (int mt = 0; mt < 4; mt++) {
            #pragma unroll
            for (int nt = 0; nt < 4; nt++) {
                int n = n0 + wn * 32 + nt * 8 + cg * 2;
                float2 b2 = *(const float2*)(bias + n);
                #pragma unroll
                for (int h = 0; h < 2; h++) {
                    long r = m0 + wm * 64 + mt * 16 + h * 8 + gr;
                    float v0 = acc[mt][nt][h * 2 + 0] + b2.x;
                    float v1 = acc[mt][nt][h * 2 + 1] + b2.y;
                    if (MODE == 1) {
                        v0 = 0.5f * v0 * (1.f + erff(v0 * 0.70710678118654752f));
                        v1 = 0.5f * v1 * (1.f + erff(v1 * 0.70710678118654752f));
                    }
                    if (MODE == 2) {
                        float2 rr = *(const float2*)(res + r * N + n);
                        v0 += rr.x; v1 += rr.y;
                    }
                    *(float2*)(out + r * N + n) = make_float2(v0, v1);
                }
            }
        }
    } else {
        // transpose through smem -> coalesced NCHW scatter
        __syncthreads();
        float* T = sm;    // [128][66]
        #pragma unroll
        for (int chunk = 0; chunk < 2; chunk++) {
            if ((wn >> 1) == chunk) {
                #pragma unroll
                for (int mt = 0; mt < 4; mt++) {
                    #pragma unroll
                    for (int nt = 0; nt < 4; nt++) {
                        int cl = (wn & 1) * 32 + nt * 8 + cg * 2;
                        int n  = n0 + chunk * 64 + cl;
                        float2 b2 = *(const float2*)(bias + n);
                        #pragma unroll
                        for (int h = 0; h < 2; h++) {
                            int rl = wm * 64 + mt * 16 + h * 8 + gr;
                            long r = m0 + rl;
                            float2 rr = *(const float2*)(res + r * 384 + n);
                            T[rl * 66 + cl]     = acc[mt][nt][h * 2 + 0] + b2.x + rr.x;
                            T[rl * 66 + cl + 1] = acc[mt][nt][h * 2 + 1] + b2.y + rr.y;
                        }
                    }
                }
            }
            __syncthreads();
            int ch = tid & 63;
            for (int g = tid >> 6; g < 16; g += 4) {
                long m = m0 + g * 8;
                int winI = (int)(m >> 6), sI = (int)(m & 63);
                int bI = winI >> 8, whI = (winI >> 4) & 15, wwI = winI & 15;
                int n = n0 + chunk * 64 + ch;
                long base = ((long)(bI * 384 + n)) * 16384
                          + (long)(whI * 8 + (sI >> 3)) * 128 + wwI * 8;
                float v[8];
                #pragma unroll
                for (int i = 0; i < 8; i++) v[i] = T[(g * 8 + i) * 66 + ch];
                *(float4*)(out + base)     = make_float4(v[0], v[1], v[2], v[3]);
                *(float4*)(out + base + 4) = make_float4(v[4], v[5], v[6], v[7]);
            }
            __syncthreads();
        }
    }
}

// ===========================================================================
// Kernel 3: attention per (window, head)
// ===========================================================================
__global__ void __launch_bounds__(256) attn_kernel(
    const float* __restrict__ QKV, float* __restrict__ O)
{
    __shared__ float qv[64][49];   // q, later v
    __shared__ float ks[64][49];
    __shared__ float p[64][65];

    int head = blockIdx.x;
    long tok0 = (long)blockIdx.y * 64;
    int tid = threadIdx.x;
    int qo = head * 48, ko = 384 + head * 48, vo = 768 + head * 48;

    for (int idx = tid; idx < 64 * 48; idx += 256) {
        int s = idx / 48, f = idx % 48;
        const float* row = QKV + (tok0 + s) * 1152;
        qv[s][f] = row[qo + f];
        ks[s][f] = row[ko + f];
    }
    __syncthreads();

    int i0 = (tid >> 4) * 4;
    int j0 = (tid & 15) * 4;
    {
        float acc[4][4] = {};
        #pragma unroll 4
        for (int d = 0; d < 48; d++) {
            float a[4], bvv[4];
            #pragma unroll
            for (int ii = 0; ii < 4; ii++) a[ii] = qv[i0 + ii][d];
            #pragma unroll
            for (int jj = 0; jj < 4; jj++) bvv[jj] = ks[j0 + jj][d];
            #pragma unroll
            for (int ii = 0; ii < 4; ii++)
                #pragma unroll
                for (int jj = 0; jj < 4; jj++)
                    acc[ii][jj] += a[ii] * bvv[jj];
        }
        const float scale = 0.14433756729740645f;   // 1/sqrt(48)
        #pragma unroll
        for (int ii = 0; ii < 4; ii++)
            #pragma unroll
            for (int jj = 0; jj < 4; jj++)
                p[i0 + ii][j0 + jj] = acc[ii][jj] * scale;
    }
    __syncthreads();

    for (int idx = tid; idx < 64 * 48; idx += 256) {
        int s = idx / 48, f = idx % 48;
        qv[s][f] = QKV[(tok0 + s) * 1152 + vo + f];
    }

    int lane = tid & 31, wd = tid >> 5;
    for (int t = wd * 8; t < wd * 8 + 8; t++) {
        float v0 = p[t][lane], v1 = p[t][lane + 32];
        float mx = fmaxf(v0, v1);
        #pragma unroll
        for (int o = 16; o; o >>= 1) mx = fmaxf(mx, __shfl_xor_sync(~0u, mx, o));
        float e0 = __expf(v0 - mx), e1 = __expf(v1 - mx);
        float sm = e0 + e1;
        #pragma unroll
        for (int o = 16; o; o >>= 1) sm += __shfl_xor_sync(~0u, sm, o);
        float inv = 1.f / sm;
        p[t][lane] = e0 * inv;
        p[t][lane + 32] = e1 * inv;
    }
    __syncthreads();

    int f0 = (tid & 15) * 3;
    float oc[4][3] = {};
    #pragma unroll 4
    for (int j = 0; j < 64; j++) {
        float a[4], bvv[3];
        #pragma unroll
        for (int ii = 0; ii < 4; ii++) a[ii] = p[i0 + ii][j];
        #pragma unroll
        for (int ff = 0; ff < 3; ff++) bvv[ff] = qv[j][f0 + ff];
        #pragma unroll
        for (int ii = 0; ii < 4; ii++)
            #pragma unroll
            for (int ff = 0; ff < 3; ff++)
                oc[ii][ff] += a[ii] * bvv[ff];
    }
    #pragma unroll
    for (int ii = 0; ii < 4; ii++)
        #pragma unroll
        for (int ff = 0; ff < 3; ff++)
            O[(tok0 + i0 + ii) * 384 + head * 48 + f0 + ff] = oc[ii][ff];
}

// ===========================================================================
// Kernel 5: LayerNorm2
// ===========================================================================
__global__ void __launch_bounds__(128) ln2_kernel(
    const float* __restrict__ Hh,
    const float* __restrict__ gw, const float* __restrict__ gb,
    float* __restrict__ Y2)
{
    long t = blockIdx.x;
    int tid = threadIdx.x;
    const float* row = Hh + t * 384;
    float v[3];
    float sum = 0.f, sq = 0.f;
    #pragma unroll
    for (int i = 0; i < 3; i++) {
        v[i] = row[tid + i * 128];
        sum += v[i]; sq += v[i] * v[i];
    }
    __shared__ float ssum[4], ssq[4];
    #pragma unroll
    for (int o = 16; o; o >>= 1) {
        sum += __shfl_xor_sync(~0u, sum, o);
        sq  += __shfl_xor_sync(~0u, sq,  o);
    }
    if ((tid & 31) == 0) { ssum[tid >> 5] = sum; ssq[tid >> 5] = sq; }
    __syncthreads();
    sum = ssum[0] + ssum[1] + ssum[2] + ssum[3];
    sq  = ssq[0]  + ssq[1]  + ssq[2]  + ssq[3];
    float m  = sum * (1.f / 384.f);
    float rs = rsqrtf(sq * (1.f / 384.f) - m * m + 1e-5f);
    #pragma unroll
    for (int i = 0; i < 3; i++) {
        int c = tid + i * 128;
        Y2[t * 384 + c] = (v[i] - m) * rs * gw[c] + gb[c];
    }
}

// ===========================================================================
extern "C" void kernel_launch(void* const* d_in, const int* in_sizes, int n_in,
                              void* d_out, int out_size)
{
    const float* x     = (const float*)d_in[0];
    const float* n1_w  = (const float*)d_in[1];
    const float* n1_b  = (const float*)d_in[2];
    const float* in_w  = (const float*)d_in[3];
    const float* in_b  = (const float*)d_in[4];
    const float* out_w = (const float*)d_in[5];
    const float* out_b = (const float*)d_in[6];
    const float* n2_w  = (const float*)d_in[7];
    const float* n2_b  = (const float*)d_in[8];
    const float* w1    = (const float*)d_in[9];
    const float* b1    = (const float*)d_in[10];
    const float* w2    = (const float*)d_in[11];
    const float* b2    = (const float*)d_in[12];
    float* out = (float*)d_out;

    float *Y, *WIN, *QKV;
    cudaGetSymbolAddress((void**)&Y,   g_bufA);
    cudaGetSymbolAddress((void**)&WIN, g_bufB);
    cudaGetSymbolAddress((void**)&QKV, g_bufC);
    float* O  = Y;                        // g_bufA reused
    float* H  = WIN;                      // g_bufB reused (elementwise alias)
    float* Y2 = QKV;                      // g_bufC front
    float* G  = QKV + (size_t)TOKS * 384; // g_bufC back

    // 1. gather + LN1
    ln1_gather_kernel<<<2048 * 4, 256>>>(x, n1_w, n1_b, Y, WIN);
    // 2. QKV projection (tf32 mma)
    mma_gemm<0><<<dim3(1152 / 128, TOKS / 128), 256>>>(Y, in_w, in_b, nullptr, QKV, 384, 1152);
    // 3. attention
    attn_kernel<<<dim3(8, 2048), 256>>>(QKV, O);
    // 4. out projection + residual -> H
    mma_gemm<2><<<dim3(384 / 128, TOKS / 128), 256>>>(O, out_w, out_b, WIN, H, 384, 384);
    // 5. LN2
    ln2_kernel<<<TOKS, 128>>>(H, n2_w, n2_b, Y2);
    // 6. MLP fc1 + gelu
    mma_gemm<1><<<dim3(768 / 128, TOKS / 128), 256>>>(Y2, w1, b1, nullptr, G, 384, 768);
    // 7. MLP fc2 + residual + window-reverse scatter
    mma_gemm<3><<<dim3(384 / 128, TOKS / 128), 256>>>(G, w2, b2, H, out, 768, 384);
}

// round 4
// speedup vs baseline: 2.8776x; 1.2220x over previous
#include <cuda_runtime.h>
#include <cuda_fp16.h>
#include <math.h>
#include <stdint.h>

#define TOKS 131072          // 2048 windows * 64 tokens

// fp32 scratch
__device__ float  g_bufB[(size_t)TOKS * 384];    // WIN, later H (residual stream)
__device__ float  g_bufC[(size_t)TOKS * 1152];   // QKV
// fp16 scratch
__device__ __half g_hA[(size_t)TOKS * 384];      // Y (post-LN1), later O (attn out)
__device__ __half g_hB[(size_t)TOKS * 1152];     // Y2 (384) + G (768)
__device__ __half g_wh[1179648];                 // all weights converted to half

// weight offsets in g_wh (halves)
#define WQKV_OFF 0
#define WO_OFF   442368
#define W1_OFF   589824
#define W2_OFF   884736

// ===========================================================================
// helpers
// ===========================================================================
__device__ __forceinline__ void cp16(uint32_t dst, const void* src) {
    asm volatile("cp.async.cg.shared.global [%0], [%1], 16;"
        :: "r"(dst), "l"(src));
}
__device__ __forceinline__ void mma16(float* d, const uint32_t* a, const uint32_t* b) {
    asm volatile(
        "mma.sync.aligned.m16n8k16.row.col.f32.f16.f16.f32 "
        "{%0,%1,%2,%3}, {%4,%5,%6,%7}, {%8,%9}, {%0,%1,%2,%3};"
        : "+f"(d[0]), "+f"(d[1]), "+f"(d[2]), "+f"(d[3])
        : "r"(a[0]), "r"(a[1]), "r"(a[2]), "r"(a[3]), "r"(b[0]), "r"(b[1]));
}

// ===========================================================================
// Kernel 0: weight fp32 -> fp16
// ===========================================================================
__global__ void __launch_bounds__(256) cvt_w_kernel(
    const float* __restrict__ s, __half* __restrict__ d, int n)
{
    int i = blockIdx.x * 256 + threadIdx.x;
    if (i < n) d[i] = __float2half(s[i]);
}

// ===========================================================================
// Kernel 1: window gather + LayerNorm1. WIN fp32, Y fp16.
// ===========================================================================
__global__ void __launch_bounds__(256) ln1_gather_kernel(
    const float* __restrict__ x,
    const float* __restrict__ gw, const float* __restrict__ gb,
    __half* __restrict__ Y, float* __restrict__ WIN)
{
    __shared__ float tile[384][17];
    __shared__ float s_mu[16], s_rs[16];

    int blk  = blockIdx.x;
    int win  = blk >> 2;
    int part = blk & 3;
    int b  = win >> 8;
    int wh = (win >> 4) & 15;
    int ww = win & 15;

    int tid = threadIdx.x;
    int sl  = tid & 15;
    int s   = part * 16 + sl;
    int r   = s >> 3, cw = s & 7;
    long xbase = (long)b * 384 * 16384 + (long)(wh * 8 + r) * 128 + ww * 8 + cw;

    for (int c = tid >> 4; c < 384; c += 16)
        tile[c][sl] = x[xbase + (long)c * 16384];
    __syncthreads();

    int lane = tid & 31, wd = tid >> 5;
    for (int t = wd * 2; t < wd * 2 + 2; t++) {
        float sum = 0.f, sq = 0.f;
        for (int c = lane; c < 384; c += 32) {
            float v = tile[c][t];
            sum += v; sq += v * v;
        }
        #pragma unroll
        for (int o = 16; o; o >>= 1) {
            sum += __shfl_xor_sync(~0u, sum, o);
            sq  += __shfl_xor_sync(~0u, sq,  o);
        }
        if (lane == 0) {
            float m = sum * (1.f / 384.f);
            float var = sq * (1.f / 384.f) - m * m;
            s_mu[t] = m;
            s_rs[t] = rsqrtf(var + 1e-5f);
        }
    }
    __syncthreads();

    long tok0 = (long)win * 64 + part * 16;
    for (int idx = tid; idx < 16 * 384; idx += 256) {
        int c = idx % 384, t = idx / 384;
        float v = tile[c][t];
        long o = (tok0 + t) * 384 + c;
        WIN[o] = v;
        Y[o] = __float2half((v - s_mu[t]) * s_rs[t] * gw[c] + gb[c]);
    }
}

// ===========================================================================
// FP16 tensor-core GEMM: OUT[M,N] = A[M,K] @ W[N,K]^T + bias (+epilogues)
// BM=128, BN=128, BK=16, 3-stage cp.async pipeline, 256 threads (8 warps).
// Warp grid 2(M)x4(N); each warp: 4 m16 x 4 n8 mma tiles (m16n8k16).
//  MODE 0: + bias, fp32 out             (QKV)
//  MODE 1: + bias, exact gelu, fp16 out (MLP1 -> G)
//  MODE 2: + bias + res, fp32 out       (attn out proj -> H)
//  MODE 3: + bias + res, fp32 window-reverse scatter to NCHW (MLP2)
// Smem: 3 stages x (A + B, each 128 rows x 12 words) = 36864 B.
// ===========================================================================
template<int MODE>
__global__ void __launch_bounds__(256, 2) mma_gemm(
    const __half* __restrict__ A, const __half* __restrict__ W,
    const float* __restrict__ bias, const float* __restrict__ res,
    void* __restrict__ outp, int K, int N)
{
    __shared__ uint32_t sm[9216];   // 36864 bytes

    const int tid  = threadIdx.x;
    const int lane = tid & 31, wid = tid >> 5;
    const int wm = wid & 1;       // M half (64 rows)
    const int wn = wid >> 1;      // N quarter (32 cols)
    const int gr = lane >> 2;     // group row 0..7
    const int cg = lane & 3;      // col-in-group 0..3

    const long m0 = (long)blockIdx.y * 128;
    const int  n0 = blockIdx.x * 128;

    const uint32_t sb = (uint32_t)__cvta_generic_to_shared(sm);
    const __half* Ag = A + m0 * K;
    const __half* Wg = W + (long)n0 * K;

    float acc[4][4][4];
    #pragma unroll
    for (int i = 0; i < 4; i++)
        #pragma unroll
        for (int j = 0; j < 4; j++)
            #pragma unroll
            for (int k = 0; k < 4; k++) acc[i][j][k] = 0.f;

    const int NS = K >> 4;
    const int row = tid >> 1, cch = tid & 1;

    // stage s -> buffer s%3. A row = 16 halves = 32B = 2x cp16.
    auto issue = [&](int s, int p) {
        cp16(sb + (p * 3072 + row * 12 + cch * 4) * 4,
             Ag + (long)row * K + s * 16 + cch * 8);
        cp16(sb + (p * 3072 + 1536 + row * 12 + cch * 4) * 4,
             Wg + (long)row * K + s * 16 + cch * 8);
        asm volatile("cp.async.commit_group;");
    };

    issue(0, 0);
    issue(1, 1);
    int p = 0;
    for (int s = 0; s < NS; s++) {
        if (s == NS - 1) asm volatile("cp.async.wait_group 0;");
        else             asm volatile("cp.async.wait_group 1;");
        __syncthreads();
        if (s + 2 < NS) {
            int p2 = p + 2; if (p2 >= 3) p2 -= 3;
            issue(s + 2, p2);
        }

        const uint32_t* As = sm + p * 3072;
        const uint32_t* Bs = As + 1536;

        uint32_t af[4][4], bf[4][2];
        #pragma unroll
        for (int mt = 0; mt < 4; mt++) {
            int r = wm * 64 + mt * 16 + gr;
            af[mt][0] = As[r * 12 + cg];
            af[mt][1] = As[(r + 8) * 12 + cg];
            af[mt][2] = As[r * 12 + cg + 4];
            af[mt][3] = As[(r + 8) * 12 + cg + 4];
        }
        #pragma unroll
        for (int nt = 0; nt < 4; nt++) {
            int rn = wn * 32 + nt * 8 + gr;
            bf[nt][0] = Bs[rn * 12 + cg];
            bf[nt][1] = Bs[rn * 12 + cg + 4];
        }
        #pragma unroll
        for (int mt = 0; mt < 4; mt++)
            #pragma unroll
            for (int nt = 0; nt < 4; nt++)
                mma16(acc[mt][nt], af[mt], bf[nt]);

        if (++p == 3) p = 0;
    }

    if (MODE != 3) {
        #pragma unroll
        for (int mt = 0; mt < 4; mt++) {
            #pragma unroll
            for (int nt = 0; nt < 4; nt++) {
                int n = n0 + wn * 32 + nt * 8 + cg * 2;
                float2 b2 = *(const float2*)(bias + n);
                #pragma unroll
                for (int h = 0; h < 2; h++) {
                    long r = m0 + wm * 64 + mt * 16 + h * 8 + gr;
                    float v0 = acc[mt][nt][h * 2 + 0] + b2.x;
                    float v1 = acc[mt][nt][h * 2 + 1] + b2.y;
                    if (MODE == 1) {
                        v0 = 0.5f * v0 * (1.f + erff(v0 * 0.70710678118654752f));
                        v1 = 0.5f * v1 * (1.f + erff(v1 * 0.70710678118654752f));
                    }
                    if (MODE == 2) {
                        float2 rr = *(const float2*)(res + r * N + n);
                        v0 += rr.x; v1 += rr.y;
                    }
                    if (MODE == 1) {
                        *(__half2*)((__half*)outp + r * N + n) =
                            __floats2half2_rn(v0, v1);
                    } else {
                        *(float2*)((float*)outp + r * N + n) = make_float2(v0, v1);
                    }
                }
            }
        }
    } else {
        // transpose through smem -> coalesced NCHW scatter
        float* out = (float*)outp;
        __syncthreads();
        float* T = (float*)sm;    // [128][66] floats = 33792B <= 36864B
        #pragma unroll
        for (int chunk = 0; chunk < 2; chunk++) {
            if ((wn >> 1) == chunk) {
                #pragma unroll
                for (int mt = 0; mt < 4; mt++) {
                    #pragma unroll
                    for (int nt = 0; nt < 4; nt++) {
                        int cl = (wn & 1) * 32 + nt * 8 + cg * 2;
                        int n  = n0 + chunk * 64 + cl;
                        float2 b2 = *(const float2*)(bias + n);
                        #pragma unroll
                        for (int h = 0; h < 2; h++) {
                            int rl = wm * 64 + mt * 16 + h * 8 + gr;
                            long r = m0 + rl;
                            float2 rr = *(const float2*)(res + r * 384 + n);
                            T[rl * 66 + cl]     = acc[mt][nt][h * 2 + 0] + b2.x + rr.x;
                            T[rl * 66 + cl + 1] = acc[mt][nt][h * 2 + 1] + b2.y + rr.y;
                        }
                    }
                }
            }
            __syncthreads();
            int ch = tid & 63;
            for (int g = tid >> 6; g < 16; g += 4) {
                long m = m0 + g * 8;
                int winI = (int)(m >> 6), sI = (int)(m & 63);
                int bI = winI >> 8, whI = (winI >> 4) & 15, wwI = winI & 15;
                int n = n0 + chunk * 64 + ch;
                long base = ((long)(bI * 384 + n)) * 16384
                          + (long)(whI * 8 + (sI >> 3)) * 128 + wwI * 8;
                float v[8];
                #pragma unroll
                for (int i = 0; i < 8; i++) v[i] = T[(g * 8 + i) * 66 + ch];
                *(float4*)(out + base)     = make_float4(v[0], v[1], v[2], v[3]);
                *(float4*)(out + base + 4) = make_float4(v[4], v[5], v[6], v[7]);
            }
            __syncthreads();
        }
    }
}

// ===========================================================================
// Kernel 3: attention per (window, head). fp32 compute, fp16 O output.
// float4-vectorized QK^T and P@V.
// ===========================================================================
__global__ void __launch_bounds__(256) attn_kernel(
    const float* __restrict__ QKV, __half* __restrict__ O)
{
    __shared__ float qv[64][52];   // q, later v (row 16B-aligned)
    __shared__ float ks[64][52];
    __shared__ float p[64][68];    // scores (row 16B-aligned)

    int head = blockIdx.x;
    long tok0 = (long)blockIdx.y * 64;
    int tid = threadIdx.x;
    int qo = head * 48, ko = 384 + head * 48, vo = 768 + head * 48;

    for (int idx = tid; idx < 64 * 48; idx += 256) {
        int s = idx / 48, f = idx % 48;
        const float* row = QKV + (tok0 + s) * 1152;
        qv[s][f] = row[qo + f];
        ks[s][f] = row[ko + f];
    }
    __syncthreads();

    int i0 = (tid >> 4) * 4;
    int j0 = (tid & 15) * 4;
    {
        float acc[4][4] = {};
        #pragma unroll 3
        for (int d = 0; d < 48; d += 4) {
            float4 a4[4], b4[4];
            #pragma unroll
            for (int ii = 0; ii < 4; ii++) a4[ii] = *(float4*)&qv[i0 + ii][d];
            #pragma unroll
            for (int jj = 0; jj < 4; jj++) b4[jj] = *(float4*)&ks[j0 + jj][d];
            #pragma unroll
            for (int ii = 0; ii < 4; ii++)
                #pragma unroll
                for (int jj = 0; jj < 4; jj++) {
                    acc[ii][jj] += a4[ii].x * b4[jj].x + a4[ii].y * b4[jj].y
                                 + a4[ii].z * b4[jj].z + a4[ii].w * b4[jj].w;
                }
        }
        const float scale = 0.14433756729740645f;   // 1/sqrt(48)
        #pragma unroll
        for (int ii = 0; ii < 4; ii++)
            *(float4*)&p[i0 + ii][j0] = make_float4(acc[ii][0] * scale,
                acc[ii][1] * scale, acc[ii][2] * scale, acc[ii][3] * scale);
    }
    __syncthreads();

    // overwrite qv with V (independent of softmax on p)
    for (int idx = tid; idx < 64 * 48; idx += 256) {
        int s = idx / 48, f = idx % 48;
        qv[s][f] = QKV[(tok0 + s) * 1152 + vo + f];
    }

    // softmax: 8 warps x 8 rows
    int lane = tid & 31, wd = tid >> 5;
    for (int t = wd * 8; t < wd * 8 + 8; t++) {
        float v0 = p[t][lane], v1 = p[t][lane + 32];
        float mx = fmaxf(v0, v1);
        #pragma unroll
        for (int o = 16; o; o >>= 1) mx = fmaxf(mx, __shfl_xor_sync(~0u, mx, o));
        float e0 = __expf(v0 - mx), e1 = __expf(v1 - mx);
        float sm = e0 + e1;
        #pragma unroll
        for (int o = 16; o; o >>= 1) sm += __shfl_xor_sync(~0u, sm, o);
        float inv = 1.f / sm;
        p[t][lane] = e0 * inv;
        p[t][lane + 32] = e1 * inv;
    }
    __syncthreads();

    // O = P @ V: 192 threads, 4 rows x 4 cols per thread, float4 over j
    if (tid < 192) {
        int ii0 = (tid / 12) * 4;
        int f0  = (tid % 12) * 4;
        float oc[4][4] = {};
        #pragma unroll 4
        for (int j = 0; j < 64; j += 4) {
            float4 pr[4];
            #pragma unroll
            for (int ii = 0; ii < 4; ii++) pr[ii] = *(float4*)&p[ii0 + ii][j];
            #pragma unroll
            for (int jj = 0; jj < 4; jj++) {
                float4 vv = *(float4*)&qv[j + jj][f0];
                const float* prf;
                #pragma unroll
                for (int ii = 0; ii < 4; ii++) {
                    prf = (const float*)&pr[ii];
                    float pe = prf[jj];
                    oc[ii][0] += pe * vv.x;
                    oc[ii][1] += pe * vv.y;
                    oc[ii][2] += pe * vv.z;
                    oc[ii][3] += pe * vv.w;
                }
            }
        }
        #pragma unroll
        for (int ii = 0; ii < 4; ii++) {
            __half* orow = O + (tok0 + ii0 + ii) * 384 + head * 48 + f0;
            #pragma unroll
            for (int ff = 0; ff < 4; ff++) orow[ff] = __float2half(oc[ii][ff]);
        }
    }
}

// ===========================================================================
// Kernel 5: LayerNorm2. fp32 in, fp16 out.
// ===========================================================================
__global__ void __launch_bounds__(128) ln2_kernel(
    const float* __restrict__ Hh,
    const float* __restrict__ gw, const float* __restrict__ gb,
    __half* __restrict__ Y2)
{
    long t = blockIdx.x;
    int tid = threadIdx.x;
    const float* row = Hh + t * 384;
    float v[3];
    float sum = 0.f, sq = 0.f;
    #pragma unroll
    for (int i = 0; i < 3; i++) {
        v[i] = row[tid + i * 128];
        sum += v[i]; sq += v[i] * v[i];
    }
    __shared__ float ssum[4], ssq[4];
    #pragma unroll
    for (int o = 16; o; o >>= 1) {
        sum += __shfl_xor_sync(~0u, sum, o);
        sq  += __shfl_xor_sync(~0u, sq,  o);
    }
    if ((tid & 31) == 0) { ssum[tid >> 5] = sum; ssq[tid >> 5] = sq; }
    __syncthreads();
    sum = ssum[0] + ssum[1] + ssum[2] + ssum[3];
    sq  = ssq[0]  + ssq[1]  + ssq[2]  + ssq[3];
    float m  = sum * (1.f / 384.f);
    float rs = rsqrtf(sq * (1.f / 384.f) - m * m + 1e-5f);
    #pragma unroll
    for (int i = 0; i < 3; i++) {
        int c = tid + i * 128;
        Y2[t * 384 + c] = __float2half((v[i] - m) * rs * gw[c] + gb[c]);
    }
}

// ===========================================================================
extern "C" void kernel_launch(void* const* d_in, const int* in_sizes, int n_in,
                              void* d_out, int out_size)
{
    const float* x     = (const float*)d_in[0];
    const float* n1_w  = (const float*)d_in[1];
    const float* n1_b  = (const float*)d_in[2];
    const float* in_w  = (const float*)d_in[3];
    const float* in_b  = (const float*)d_in[4];
    const float* out_w = (const float*)d_in[5];
    const float* out_b = (const float*)d_in[6];
    const float* n2_w  = (const float*)d_in[7];
    const float* n2_b  = (const float*)d_in[8];
    const float* w1    = (const float*)d_in[9];
    const float* b1    = (const float*)d_in[10];
    const float* w2    = (const float*)d_in[11];
    const float* b2    = (const float*)d_in[12];
    float* out = (float*)d_out;

    float *WIN, *QKV;
    __half *Yh, *Hb, *Wh;
    cudaGetSymbolAddress((void**)&WIN, g_bufB);
    cudaGetSymbolAddress((void**)&QKV, g_bufC);
    cudaGetSymbolAddress((void**)&Yh,  g_hA);
    cudaGetSymbolAddress((void**)&Hb,  g_hB);
    cudaGetSymbolAddress((void**)&Wh,  g_wh);

    __half* Oh  = Yh;                       // alias: Y dead after QKV gemm
    float*  H   = WIN;                      // in-place residual (1:1 elementwise)
    __half* Y2h = Hb;
    __half* Gh  = Hb + (size_t)TOKS * 384;

    // 0. convert weights to fp16
    cvt_w_kernel<<<(442368 + 255) / 256, 256>>>(in_w,  Wh + WQKV_OFF, 442368);
    cvt_w_kernel<<<(147456 + 255) / 256, 256>>>(out_w, Wh + WO_OFF,   147456);
    cvt_w_kernel<<<(294912 + 255) / 256, 256>>>(w1,    Wh + W1_OFF,   294912);
    cvt_w_kernel<<<(294912 + 255) / 256, 256>>>(w2,    Wh + W2_OFF,   294912);

    // 1. gather + LN1
    ln1_gather_kernel<<<2048 * 4, 256>>>(x, n1_w, n1_b, Yh, WIN);
    // 2. QKV projection (fp16 mma, fp32 out)
    mma_gemm<0><<<dim3(1152 / 128, TOKS / 128), 256>>>(Yh, Wh + WQKV_OFF, in_b, nullptr, QKV, 384, 1152);
    // 3. attention (fp16 O out)
    attn_kernel<<<dim3(8, 2048), 256>>>(QKV, Oh);
    // 4. out projection + residual -> H (fp32)
    mma_gemm<2><<<dim3(384 / 128, TOKS / 128), 256>>>(Oh, Wh + WO_OFF, out_b, WIN, H, 384, 384);
    // 5. LN2 (fp16 out)
    ln2_kernel<<<TOKS, 128>>>(H, n2_w, n2_b, Y2h);
    // 6. MLP fc1 + gelu (fp16 out)
    mma_gemm<1><<<dim3(768 / 128, TOKS / 128), 256>>>(Y2h, Wh + W1_OFF, b1, nullptr, Gh, 384, 768);
    // 7. MLP fc2 + residual + window-reverse scatter (fp32 out)
    mma_gemm<3><<<dim3(384 / 128, TOKS / 128), 256>>>(Gh, Wh + W2_OFF, b2, H, out, 768, 384);
}

// round 5
// speedup vs baseline: 4.5408x; 1.5780x over previous
#include <cuda_runtime.h>
#include <cuda_fp16.h>
#include <math.h>
#include <stdint.h>

#define TOKS 131072          // 2048 windows * 64 tokens

// fp32 scratch
__device__ float  g_bufB[(size_t)TOKS * 384];    // WIN, later H (residual stream)
// fp16 scratch
__device__ __half g_hA[(size_t)TOKS * 384];      // Y (post-LN1), later O (attn out)
__device__ __half g_hB[(size_t)TOKS * 1152];     // QKV, later Y2 (384) + G (768)
__device__ __half g_wh[1179648];                 // weights converted to half

#define WQKV_OFF 0
#define WO_OFF   442368
#define W1_OFF   589824
#define W2_OFF   884736

// ===========================================================================
// helpers
// ===========================================================================
__device__ __forceinline__ void cp16(uint32_t dst, const void* src) {
    asm volatile("cp.async.cg.shared.global [%0], [%1], 16;"
        :: "r"(dst), "l"(src));
}
__device__ __forceinline__ void mma16(float* d, uint32_t a0, uint32_t a1,
                                      uint32_t a2, uint32_t a3,
                                      uint32_t b0, uint32_t b1) {
    asm volatile(
        "mma.sync.aligned.m16n8k16.row.col.f32.f16.f16.f32 "
        "{%0,%1,%2,%3}, {%4,%5,%6,%7}, {%8,%9}, {%0,%1,%2,%3};"
        : "+f"(d[0]), "+f"(d[1]), "+f"(d[2]), "+f"(d[3])
        : "r"(a0), "r"(a1), "r"(a2), "r"(a3), "r"(b0), "r"(b1));
}
__device__ __forceinline__ void ldsm4(uint32_t* r, uint32_t addr) {
    asm volatile("ldmatrix.sync.aligned.m8n8.x4.shared.b16 {%0,%1,%2,%3}, [%4];"
        : "=r"(r[0]), "=r"(r[1]), "=r"(r[2]), "=r"(r[3]) : "r"(addr));
}
__device__ __forceinline__ uint32_t pack2(float a, float b) {
    __half2 h = __floats2half2_rn(a, b);
    return *(uint32_t*)&h;
}

// ===========================================================================
// Kernel 0: weight fp32 -> fp16
// ===========================================================================
__global__ void __launch_bounds__(256) cvt_w_kernel(
    const float* __restrict__ s, __half* __restrict__ d, int n)
{
    int i = blockIdx.x * 256 + threadIdx.x;
    if (i < n) d[i] = __float2half(s[i]);
}

// ===========================================================================
// Kernel 1: window gather + LayerNorm1. WIN fp32, Y fp16.
// ===========================================================================
__global__ void __launch_bounds__(256) ln1_gather_kernel(
    const float* __restrict__ x,
    const float* __restrict__ gw, const float* __restrict__ gb,
    __half* __restrict__ Y, float* __restrict__ WIN)
{
    __shared__ float tile[384][17];
    __shared__ float s_mu[16], s_rs[16];

    int blk  = blockIdx.x;
    int win  = blk >> 2;
    int part = blk & 3;
    int b  = win >> 8;
    int wh = (win >> 4) & 15;
    int ww = win & 15;

    int tid = threadIdx.x;
    int sl  = tid & 15;
    int s   = part * 16 + sl;
    int r   = s >> 3, cw = s & 7;
    long xbase = (long)b * 384 * 16384 + (long)(wh * 8 + r) * 128 + ww * 8 + cw;

    for (int c = tid >> 4; c < 384; c += 16)
        tile[c][sl] = x[xbase + (long)c * 16384];
    __syncthreads();

    int lane = tid & 31, wd = tid >> 5;
    for (int t = wd * 2; t < wd * 2 + 2; t++) {
        float sum = 0.f, sq = 0.f;
        for (int c = lane; c < 384; c += 32) {
            float v = tile[c][t];
            sum += v; sq += v * v;
        }
        #pragma unroll
        for (int o = 16; o; o >>= 1) {
            sum += __shfl_xor_sync(~0u, sum, o);
            sq  += __shfl_xor_sync(~0u, sq,  o);
        }
        if (lane == 0) {
            float m = sum * (1.f / 384.f);
            float var = sq * (1.f / 384.f) - m * m;
            s_mu[t] = m;
            s_rs[t] = rsqrtf(var + 1e-5f);
        }
    }
    __syncthreads();

    long tok0 = (long)win * 64 + part * 16;
    for (int idx = tid; idx < 16 * 384; idx += 256) {
        int c = idx % 384, t = idx / 384;
        float v = tile[c][t];
        long o = (tok0 + t) * 384 + c;
        WIN[o] = v;
        Y[o] = __float2half((v - s_mu[t]) * s_rs[t] * gw[c] + gb[c]);
    }
}

// ===========================================================================
// FP16 tensor-core GEMM: OUT[M,N] = A[M,K] @ W[N,K]^T + bias (+epilogues)
// BM=128, BN=128, BK=32, 3-stage cp.async, 256 threads, ldmatrix + swizzle.
// Swizzle: logical (row, 16B-chunk c of 4) -> line=row>>1,
//          unit = ((row&1)*4 + c) ^ (line & 7); byte = line*128 + unit*16.
//  MODE 0: + bias, fp16 out             (QKV)
//  MODE 1: + bias, exact gelu, fp16 out (MLP1 -> G)
//  MODE 2: + bias + res, fp32 out       (attn out proj -> H)
//  MODE 3: + bias + res, fp32 window-reverse scatter to NCHW (MLP2)
// Smem: 3 stages x (A 8KB + B 8KB) = 49152 B.
// ===========================================================================
template<int MODE>
__global__ void __launch_bounds__(256, 2) mma_gemm(
    const __half* __restrict__ A, const __half* __restrict__ W,
    const float* __restrict__ bias, const float* __restrict__ res,
    void* __restrict__ outp, int K, int N)
{
    __shared__ uint32_t sm[12288];   // 49152 bytes

    const int tid  = threadIdx.x;
    const int lane = tid & 31, wid = tid >> 5;
    const int wm = wid & 1;       // M half (64 rows)
    const int wn = wid >> 1;      // N quarter (32 cols)
    const int gr = lane >> 2;     // group row 0..7
    const int cg = lane & 3;      // col-in-group 0..3

    const long m0 = (long)blockIdx.y * 128;
    const int  n0 = blockIdx.x * 128;

    const uint32_t sb = (uint32_t)__cvta_generic_to_shared(sm);
    const __half* Ag = A + m0 * K;
    const __half* Wg = W + (long)n0 * K;

    float acc[4][4][4];
    #pragma unroll
    for (int i = 0; i < 4; i++)
        #pragma unroll
        for (int j = 0; j < 4; j++)
            #pragma unroll
            for (int k = 0; k < 4; k++) acc[i][j][k] = 0.f;

    const int NS = K >> 5;

    // stage load: 128 rows x 4 chunks (16B) per matrix; 512 chunks / 256 thr
    auto issue = [&](int s, int p) {
        #pragma unroll
        for (int i = 0; i < 2; i++) {
            int idx = tid + i * 256;
            int row = idx >> 2, c = idx & 3;
            int line = row >> 1;
            uint32_t u = (uint32_t)((((row & 1) << 2) + c) ^ (line & 7));
            uint32_t off = p * 16384u + line * 128u + u * 16u;
            cp16(sb + off,          Ag + (long)row * K + s * 32 + c * 8);
            cp16(sb + 8192u + off,  Wg + (long)row * K + s * 32 + c * 8);
        }
        asm volatile("cp.async.commit_group;");
    };

    // ldmatrix lane-address components
    const int lrow = (lane & 7) + ((lane >> 3) & 1) * 8;   // row within 16
    const int lk   = lane >> 4;                            // k-chunk half

    issue(0, 0);
    issue(1, 1);
    int p = 0;
    for (int s = 0; s < NS; s++) {
        if (s == NS - 1) asm volatile("cp.async.wait_group 0;");
        else             asm volatile("cp.async.wait_group 1;");
        __syncthreads();
        if (s + 2 < NS) {
            int p2 = p + 2; if (p2 >= 3) p2 -= 3;
            issue(s + 2, p2);
        }

        const uint32_t abase = sb + p * 16384u;
        const uint32_t bbase = abase + 8192u;

        #pragma unroll
        for (int kc = 0; kc < 2; kc++) {
            int c = kc * 2 + lk;
            uint32_t af[4][4], bq[2][4];
            #pragma unroll
            for (int mt = 0; mt < 4; mt++) {
                int row = wm * 64 + mt * 16 + lrow;
                int line = row >> 1;
                uint32_t u = (uint32_t)((((row & 1) << 2) + c) ^ (line & 7));
                ldsm4(af[mt], abase + line * 128u + u * 16u);
            }
            #pragma unroll
            for (int pr = 0; pr < 2; pr++) {
                int row = wn * 32 + pr * 16 + lrow;
                int line = row >> 1;
                uint32_t u = (uint32_t)((((row & 1) << 2) + c) ^ (line & 7));
                ldsm4(bq[pr], bbase + line * 128u + u * 16u);
            }
            #pragma unroll
            for (int mt = 0; mt < 4; mt++)
                #pragma unroll
                for (int nt = 0; nt < 4; nt++) {
                    int pr = nt >> 1, hi = nt & 1;
                    mma16(acc[mt][nt], af[mt][0], af[mt][1], af[mt][2], af[mt][3],
                          bq[pr][hi], bq[pr][hi + 2]);
                }
        }
        if (++p == 3) p = 0;
    }

    if (MODE != 3) {
        #pragma unroll
        for (int mt = 0; mt < 4; mt++) {
            #pragma unroll
            for (int nt = 0; nt < 4; nt++) {
                int n = n0 + wn * 32 + nt * 8 + cg * 2;
                float2 b2 = *(const float2*)(bias + n);
                #pragma unroll
                for (int h = 0; h < 2; h++) {
                    long r = m0 + wm * 64 + mt * 16 + h * 8 + gr;
                    float v0 = acc[mt][nt][h * 2 + 0] + b2.x;
                    float v1 = acc[mt][nt][h * 2 + 1] + b2.y;
                    if (MODE == 1) {
                        v0 = 0.5f * v0 * (1.f + erff(v0 * 0.70710678118654752f));
                        v1 = 0.5f * v1 * (1.f + erff(v1 * 0.70710678118654752f));
                    }
                    if (MODE == 2) {
                        float2 rr = *(const float2*)(res + r * N + n);
                        v0 += rr.x; v1 += rr.y;
                        *(float2*)((float*)outp + r * N + n) = make_float2(v0, v1);
                    } else {
                        *(uint32_t*)((__half*)outp + r * N + n) = pack2(v0, v1);
                    }
                }
            }
        }
    } else {
        // transpose through smem -> coalesced NCHW scatter
        float* out = (float*)outp;
        __syncthreads();
        float* T = (float*)sm;    // [128][66] floats = 33792B
        #pragma unroll
        for (int chunk = 0; chunk < 2; chunk++) {
            if ((wn >> 1) == chunk) {
                #pragma unroll
                for (int mt = 0; mt < 4; mt++) {
                    #pragma unroll
                    for (int nt = 0; nt < 4; nt++) {
                        int cl = (wn & 1) * 32 + nt * 8 + cg * 2;
                        int n  = n0 + chunk * 64 + cl;
                        float2 b2 = *(const float2*)(bias + n);
                        #pragma unroll
                        for (int h = 0; h < 2; h++) {
                            int rl = wm * 64 + mt * 16 + h * 8 + gr;
                            long r = m0 + rl;
                            float2 rr = *(const float2*)(res + r * 384 + n);
                            T[rl * 66 + cl]     = acc[mt][nt][h * 2 + 0] + b2.x + rr.x;
                            T[rl * 66 + cl + 1] = acc[mt][nt][h * 2 + 1] + b2.y + rr.y;
                        }
                    }
                }
            }
            __syncthreads();
            int ch = tid & 63;
            for (int g = tid >> 6; g < 16; g += 4) {
                long m = m0 + g * 8;
                int winI = (int)(m >> 6), sI = (int)(m & 63);
                int bI = winI >> 8, whI = (winI >> 4) & 15, wwI = winI & 15;
                int n = n0 + chunk * 64 + ch;
                long base = ((long)(bI * 384 + n)) * 16384
                          + (long)(whI * 8 + (sI >> 3)) * 128 + wwI * 8;
                float v[8];
                #pragma unroll
                for (int i = 0; i < 8; i++) v[i] = T[(g * 8 + i) * 66 + ch];
                *(float4*)(out + base)     = make_float4(v[0], v[1], v[2], v[3]);
                *(float4*)(out + base + 4) = make_float4(v[4], v[5], v[6], v[7]);
            }
            __syncthreads();
        }
    }
}

// ===========================================================================
// Kernel 3: tensor-core attention per (window, head). 128 threads, 4 warps.
// Warp w: rows 16w..16w+15. S=QK^T (fp32 acc) -> register softmax ->
// C->A fragment repack -> P@V -> fp16 O.
// ===========================================================================
__global__ void __launch_bounds__(128) attn_kernel(
    const __half* __restrict__ QKV, __half* __restrict__ O)
{
    __shared__ __half qs[64 * 50];
    __shared__ __half ks[64 * 50];
    __shared__ __half vt[48 * 66];

    int head = blockIdx.x;
    long tok0 = (long)blockIdx.y * 64;
    int tid = threadIdx.x;
    int lane = tid & 31, wrp = tid >> 5;
    const __half* base = QKV + tok0 * 1152 + head * 48;

    for (int i = tid; i < 64 * 24; i += 128) {
        int t = i / 24, f2 = i % 24;
        *(uint32_t*)&qs[t * 50 + f2 * 2] =
            *(const uint32_t*)(base + (long)t * 1152 + f2 * 2);
        *(uint32_t*)&ks[t * 50 + f2 * 2] =
            *(const uint32_t*)(base + 384 + (long)t * 1152 + f2 * 2);
        uint32_t w = *(const uint32_t*)(base + 768 + (long)t * 1152 + f2 * 2);
        __half2 h = *(__half2*)&w;
        vt[(f2 * 2) * 66 + t]     = __low2half(h);
        vt[(f2 * 2 + 1) * 66 + t] = __high2half(h);
    }
    __syncthreads();

    int gr = lane >> 2, cg = lane & 3;
    int m0 = wrp * 16;

    // --- S = Q K^T : 8 n-tiles, fp32 acc
    float sacc[8][4];
    #pragma unroll
    for (int nt = 0; nt < 8; nt++)
        #pragma unroll
        for (int j = 0; j < 4; j++) sacc[nt][j] = 0.f;

    #pragma unroll
    for (int kc = 0; kc < 3; kc++) {
        uint32_t a0 = *(uint32_t*)&qs[(m0 + gr) * 50 + kc * 16 + cg * 2];
        uint32_t a1 = *(uint32_t*)&qs[(m0 + gr + 8) * 50 + kc * 16 + cg * 2];
        uint32_t a2 = *(uint32_t*)&qs[(m0 + gr) * 50 + kc * 16 + 8 + cg * 2];
        uint32_t a3 = *(uint32_t*)&qs[(m0 + gr + 8) * 50 + kc * 16 + 8 + cg * 2];
        #pragma unroll
        for (int nt = 0; nt < 8; nt++) {
            uint32_t b0 = *(uint32_t*)&ks[(nt * 8 + gr) * 50 + kc * 16 + cg * 2];
            uint32_t b1 = *(uint32_t*)&ks[(nt * 8 + gr) * 50 + kc * 16 + 8 + cg * 2];
            mma16(sacc[nt], a0, a1, a2, a3, b0, b1);
        }
    }

    // --- register softmax (rows gr and gr+8), scale = 1/sqrt(48)
    const float scale = 0.14433756729740645f;
    float mx0 = -1e30f, mx1 = -1e30f;
    #pragma unroll
    for (int nt = 0; nt < 8; nt++) {
        mx0 = fmaxf(mx0, fmaxf(sacc[nt][0], sacc[nt][1]));
        mx1 = fmaxf(mx1, fmaxf(sacc[nt][2], sacc[nt][3]));
    }
    mx0 = fmaxf(mx0, __shfl_xor_sync(~0u, mx0, 1));
    mx0 = fmaxf(mx0, __shfl_xor_sync(~0u, mx0, 2));
    mx1 = fmaxf(mx1, __shfl_xor_sync(~0u, mx1, 1));
    mx1 = fmaxf(mx1, __shfl_xor_sync(~0u, mx1, 2));
    mx0 *= scale; mx1 *= scale;

    float e[8][4];
    float sum0 = 0.f, sum1 = 0.f;
    #pragma unroll
    for (int nt = 0; nt < 8; nt++) {
        e[nt][0] = __expf(sacc[nt][0] * scale - mx0);
        e[nt][1] = __expf(sacc[nt][1] * scale - mx0);
        e[nt][2] = __expf(sacc[nt][2] * scale - mx1);
        e[nt][3] = __expf(sacc[nt][3] * scale - mx1);
        sum0 += e[nt][0] + e[nt][1];
        sum1 += e[nt][2] + e[nt][3];
    }
    sum0 += __shfl_xor_sync(~0u, sum0, 1);
    sum0 += __shfl_xor_sync(~0u, sum0, 2);
    sum1 += __shfl_xor_sync(~0u, sum1, 1);
    sum1 += __shfl_xor_sync(~0u, sum1, 2);
    float inv0 = 1.f / sum0, inv1 = 1.f / sum1;

    uint32_t p0[8], p1[8];
    #pragma unroll
    for (int nt = 0; nt < 8; nt++) {
        p0[nt] = pack2(e[nt][0] * inv0, e[nt][1] * inv0);
        p1[nt] = pack2(e[nt][2] * inv1, e[nt][3] * inv1);
    }

    // --- O = P @ V : 4 k-chunks (keys), 6 n-tiles (features)
    float oacc[6][4];
    #pragma unroll
    for (int nt = 0; nt < 6; nt++)
        #pragma unroll
        for (int j = 0; j < 4; j++) oacc[nt][j] = 0.f;

    #pragma unroll
    for (int kc = 0; kc < 4; kc++) {
        uint32_t a0 = p0[2 * kc],     a1 = p1[2 * kc];
        uint32_t a2 = p0[2 * kc + 1], a3 = p1[2 * kc + 1];
        #pragma unroll
        for (int nt = 0; nt < 6; nt++) {
            uint32_t b0 = *(uint32_t*)&vt[(nt * 8 + gr) * 66 + kc * 16 + cg * 2];
            uint32_t b1 = *(uint32_t*)&vt[(nt * 8 + gr) * 66 + kc * 16 + 8 + cg * 2];
            mma16(oacc[nt], a0, a1, a2, a3, b0, b1);
        }
    }

    #pragma unroll
    for (int nt = 0; nt < 6; nt++) {
        long col = head * 48 + nt * 8 + cg * 2;
        *(uint32_t*)(O + (tok0 + m0 + gr) * 384 + col)     = pack2(oacc[nt][0], oacc[nt][1]);
        *(uint32_t*)(O + (tok0 + m0 + gr + 8) * 384 + col) = pack2(oacc[nt][2], oacc[nt][3]);
    }
}

// ===========================================================================
// Kernel 5: LayerNorm2. fp32 in, fp16 out.
// ===========================================================================
__global__ void __launch_bounds__(128) ln2_kernel(
    const float* __restrict__ Hh,
    const float* __restrict__ gw, const float* __restrict__ gb,
    __half* __restrict__ Y2)
{
    long t = blockIdx.x;
    int tid = threadIdx.x;
    const float* row = Hh + t * 384;
    float v[3];
    float sum = 0.f, sq = 0.f;
    #pragma unroll
    for (int i = 0; i < 3; i++) {
        v[i] = row[tid + i * 128];
        sum += v[i]; sq += v[i] * v[i];
    }
    __shared__ float ssum[4], ssq[4];
    #pragma unroll
    for (int o = 16; o; o >>= 1) {
        sum += __shfl_xor_sync(~0u, sum, o);
        sq  += __shfl_xor_sync(~0u, sq,  o);
    }
    if ((tid & 31) == 0) { ssum[tid >> 5] = sum; ssq[tid >> 5] = sq; }
    __syncthreads();
    sum = ssum[0] + ssum[1] + ssum[2] + ssum[3];
    sq  = ssq[0]  + ssq[1]  + ssq[2]  + ssq[3];
    float m  = sum * (1.f / 384.f);
    float rs = rsqrtf(sq * (1.f / 384.f) - m * m + 1e-5f);
    #pragma unroll
    for (int i = 0; i < 3; i++) {
        int c = tid + i * 128;
        Y2[t * 384 + c] = __float2half((v[i] - m) * rs * gw[c] + gb[c]);
    }
}

// ===========================================================================
extern "C" void kernel_launch(void* const* d_in, const int* in_sizes, int n_in,
                              void* d_out, int out_size)
{
    const float* x     = (const float*)d_in[0];
    const float* n1_w  = (const float*)d_in[1];
    const float* n1_b  = (const float*)d_in[2];
    const float* in_w  = (const float*)d_in[3];
    const float* in_b  = (const float*)d_in[4];
    const float* out_w = (const float*)d_in[5];
    const float* out_b = (const float*)d_in[6];
    const float* n2_w  = (const float*)d_in[7];
    const float* n2_b  = (const float*)d_in[8];
    const float* w1    = (const float*)d_in[9];
    const float* b1    = (const float*)d_in[10];
    const float* w2    = (const float*)d_in[11];
    const float* b2    = (const float*)d_in[12];
    float* out = (float*)d_out;

    float *WIN;
    __half *Yh, *Hb, *Wh;
    cudaGetSymbolAddress((void**)&WIN, g_bufB);
    cudaGetSymbolAddress((void**)&Yh,  g_hA);
    cudaGetSymbolAddress((void**)&Hb,  g_hB);
    cudaGetSymbolAddress((void**)&Wh,  g_wh);

    __half* QKVh = Hb;                      // lifetime: steps 2-3
    __half* Oh   = Yh;                      // alias: Y dead after QKV gemm
    float*  H    = WIN;                     // in-place residual
    __half* Y2h  = Hb;                      // lifetime: steps 5-6 (QKV dead)
    __half* Gh   = Hb + (size_t)TOKS * 384;

    // 0. convert weights to fp16
    cvt_w_kernel<<<(442368 + 255) / 256, 256>>>(in_w,  Wh + WQKV_OFF, 442368);
    cvt_w_kernel<<<(147456 + 255) / 256, 256>>>(out_w, Wh + WO_OFF,   147456);
    cvt_w_kernel<<<(294912 + 255) / 256, 256>>>(w1,    Wh + W1_OFF,   294912);
    cvt_w_kernel<<<(294912 + 255) / 256, 256>>>(w2,    Wh + W2_OFF,   294912);

    // 1. gather + LN1
    ln1_gather_kernel<<<2048 * 4, 256>>>(x, n1_w, n1_b, Yh, WIN);
    // 2. QKV projection (fp16 in/out)
    mma_gemm<0><<<dim3(1152 / 128, TOKS / 128), 256>>>(Yh, Wh + WQKV_OFF, in_b, nullptr, QKVh, 384, 1152);
    // 3. tensor-core attention (fp16 O out)
    attn_kernel<<<dim3(8, 2048), 128>>>(QKVh, Oh);
    // 4. out projection + residual -> H (fp32)
    mma_gemm<2><<<dim3(384 / 128, TOKS / 128), 256>>>(Oh, Wh + WO_OFF, out_b, WIN, H, 384, 384);
    // 5. LN2 (fp16 out)
    ln2_kernel<<<TOKS, 128>>>(H, n2_w, n2_b, Y2h);
    // 6. MLP fc1 + gelu (fp16 out)
    mma_gemm<1><<<dim3(768 / 128, TOKS / 128), 256>>>(Y2h, Wh + W1_OFF, b1, nullptr, Gh, 384, 768);
    // 7. MLP fc2 + residual + window-reverse scatter (fp32 out)
    mma_gemm<3><<<dim3(384 / 128, TOKS / 128), 256>>>(Gh, Wh + W2_OFF, b2, H, out, 768, 384);
}

// round 6
// speedup vs baseline: 4.6773x; 1.0300x over previous
#include <cuda_runtime.h>
#include <cuda_fp16.h>
#include <math.h>
#include <stdint.h>

#define TOKS 131072          // 2048 windows * 64 tokens

// fp16 scratch
__device__ __half g_hR[(size_t)TOKS * 384];      // WIN, later H (residual, fp16)
__device__ __half g_hA[(size_t)TOKS * 384];      // Y (post-LN1), later O (attn out)
__device__ __half g_hB[(size_t)TOKS * 1152];     // QKV, later Y2 (384) + G (768)
__device__ __half g_wh[1179648];                 // weights converted to half

#define WQKV_OFF 0
#define WO_OFF   442368
#define W1_OFF   589824
#define W2_OFF   884736

#define GEMM_SMEM 65536

// ===========================================================================
// helpers
// ===========================================================================
__device__ __forceinline__ void cp16(uint32_t dst, const void* src) {
    asm volatile("cp.async.cg.shared.global [%0], [%1], 16;"
        :: "r"(dst), "l"(src));
}
__device__ __forceinline__ void mma16(float* d, uint32_t a0, uint32_t a1,
                                      uint32_t a2, uint32_t a3,
                                      uint32_t b0, uint32_t b1) {
    asm volatile(
        "mma.sync.aligned.m16n8k16.row.col.f32.f16.f16.f32 "
        "{%0,%1,%2,%3}, {%4,%5,%6,%7}, {%8,%9}, {%0,%1,%2,%3};"
        : "+f"(d[0]), "+f"(d[1]), "+f"(d[2]), "+f"(d[3])
        : "r"(a0), "r"(a1), "r"(a2), "r"(a3), "r"(b0), "r"(b1));
}
__device__ __forceinline__ void ldsm4(uint32_t* r, uint32_t addr) {
    asm volatile("ldmatrix.sync.aligned.m8n8.x4.shared.b16 {%0,%1,%2,%3}, [%4];"
        : "=r"(r[0]), "=r"(r[1]), "=r"(r[2]), "=r"(r[3]) : "r"(addr));
}
__device__ __forceinline__ uint32_t pack2(float a, float b) {
    __half2 h = __floats2half2_rn(a, b);
    return *(uint32_t*)&h;
}
__device__ __forceinline__ float2 unpack2(uint32_t u) {
    return __half22float2(*(__half2*)&u);
}

// ===========================================================================
// Kernel 0: all weights fp32 -> fp16 in one launch
// ===========================================================================
__global__ void __launch_bounds__(256) cvt_all_kernel(
    const float* __restrict__ a, const float* __restrict__ b,
    const float* __restrict__ c, const float* __restrict__ d,
    __half* __restrict__ o)
{
    int i = blockIdx.x * 256 + threadIdx.x;
    if (i < 442368)       o[i] = __float2half(a[i]);
    else if (i < 589824)  o[i] = __float2half(b[i - 442368]);
    else if (i < 884736)  o[i] = __float2half(c[i - 589824]);
    else if (i < 1179648) o[i] = __float2half(d[i - 884736]);
}

// ===========================================================================
// Kernel 1: window gather + LayerNorm1. WIN fp16, Y fp16.
// ===========================================================================
__global__ void __launch_bounds__(256) ln1_gather_kernel(
    const float* __restrict__ x,
    const float* __restrict__ gw, const float* __restrict__ gb,
    __half* __restrict__ Y, __half* __restrict__ WIN)
{
    __shared__ float tile[384][17];
    __shared__ float s_mu[16], s_rs[16];

    int blk  = blockIdx.x;
    int win  = blk >> 2;
    int part = blk & 3;
    int b  = win >> 8;
    int wh = (win >> 4) & 15;
    int ww = win & 15;

    int tid = threadIdx.x;
    int sl  = tid & 15;
    int s   = part * 16 + sl;
    int r   = s >> 3, cw = s & 7;
    long xbase = (long)b * 384 * 16384 + (long)(wh * 8 + r) * 128 + ww * 8 + cw;

    for (int c = tid >> 4; c < 384; c += 16)
        tile[c][sl] = x[xbase + (long)c * 16384];
    __syncthreads();

    int lane = tid & 31, wd = tid >> 5;
    for (int t = wd * 2; t < wd * 2 + 2; t++) {
        float sum = 0.f, sq = 0.f;
        for (int c = lane; c < 384; c += 32) {
            float v = tile[c][t];
            sum += v; sq += v * v;
        }
        #pragma unroll
        for (int o = 16; o; o >>= 1) {
            sum += __shfl_xor_sync(~0u, sum, o);
            sq  += __shfl_xor_sync(~0u, sq,  o);
        }
        if (lane == 0) {
            float m = sum * (1.f / 384.f);
            float var = sq * (1.f / 384.f) - m * m;
            s_mu[t] = m;
            s_rs[t] = rsqrtf(var + 1e-5f);
        }
    }
    __syncthreads();

    long tok0 = (long)win * 64 + part * 16;
    for (int idx = tid; idx < 16 * 384; idx += 256) {
        int c = idx % 384, t = idx / 384;
        float v = tile[c][t];
        long o = (tok0 + t) * 384 + c;
        WIN[o] = __float2half(v);
        Y[o] = __float2half((v - s_mu[t]) * s_rs[t] * gw[c] + gb[c]);
    }
}

// ===========================================================================
// FP16 tensor-core GEMM: OUT[M,N] = A[M,K] @ W[N,K]^T + bias (+epilogues)
// BM=128, BN=128, BK=32, 4-stage cp.async, 256 threads, ldmatrix + swizzle.
//  MODE 0: + bias, fp16 out             (QKV)
//  MODE 1: + bias, exact gelu, fp16 out (MLP1 -> G)
//  MODE 2: + bias + res(fp16), fp16 out (attn out proj -> H)
//  MODE 3: + bias + res(fp16), fp32 window-reverse scatter to NCHW (MLP2)
// Dynamic smem: 4 stages x (A 8KB + B 8KB) = 65536 B.
// ===========================================================================
template<int MODE>
__global__ void __launch_bounds__(256, 2) mma_gemm(
    const __half* __restrict__ A, const __half* __restrict__ W,
    const float* __restrict__ bias, const __half* __restrict__ res,
    void* __restrict__ outp, int K, int N)
{
    extern __shared__ uint32_t sm[];

    const int tid  = threadIdx.x;
    const int lane = tid & 31, wid = tid >> 5;
    const int wm = wid & 1;       // M half (64 rows)
    const int wn = wid >> 1;      // N quarter (32 cols)
    const int gr = lane >> 2;     // group row 0..7
    const int cg = lane & 3;      // col-in-group 0..3

    const long m0 = (long)blockIdx.y * 128;
    const int  n0 = blockIdx.x * 128;

    const uint32_t sb = (uint32_t)__cvta_generic_to_shared(sm);
    const __half* Ag = A + m0 * K;
    const __half* Wg = W + (long)n0 * K;

    float acc[4][4][4];
    #pragma unroll
    for (int i = 0; i < 4; i++)
        #pragma unroll
        for (int j = 0; j < 4; j++)
            #pragma unroll
            for (int k = 0; k < 4; k++) acc[i][j][k] = 0.f;

    const int NS = K >> 5;

    // stage load: 128 rows x 4 chunks (16B) per matrix; swizzled lines
    auto issue = [&](int s, int p) {
        #pragma unroll
        for (int i = 0; i < 2; i++) {
            int idx = tid + i * 256;
            int row = idx >> 2, c = idx & 3;
            int line = row >> 1;
            uint32_t u = (uint32_t)((((row & 1) << 2) + c) ^ (line & 7));
            uint32_t off = p * 16384u + line * 128u + u * 16u;
            cp16(sb + off,          Ag + (long)row * K + s * 32 + c * 8);
            cp16(sb + 8192u + off,  Wg + (long)row * K + s * 32 + c * 8);
        }
        asm volatile("cp.async.commit_group;");
    };

    const int lrow = (lane & 7) + ((lane >> 3) & 1) * 8;
    const int lk   = lane >> 4;

    issue(0, 0);
    issue(1, 1);
    issue(2, 2);
    int p = 0;
    for (int s = 0; s < NS; s++) {
        if (s + 2 < NS)      asm volatile("cp.async.wait_group 2;");
        else if (s + 1 < NS) asm volatile("cp.async.wait_group 1;");
        else                 asm volatile("cp.async.wait_group 0;");
        __syncthreads();
        if (s + 3 < NS) issue(s + 3, (s + 3) & 3);

        const uint32_t abase = sb + p * 16384u;
        const uint32_t bbase = abase + 8192u;

        #pragma unroll
        for (int kc = 0; kc < 2; kc++) {
            int c = kc * 2 + lk;
            uint32_t af[4][4], bq[2][4];
            #pragma unroll
            for (int mt = 0; mt < 4; mt++) {
                int row = wm * 64 + mt * 16 + lrow;
                int line = row >> 1;
                uint32_t u = (uint32_t)((((row & 1) << 2) + c) ^ (line & 7));
                ldsm4(af[mt], abase + line * 128u + u * 16u);
            }
            #pragma unroll
            for (int pr = 0; pr < 2; pr++) {
                int row = wn * 32 + pr * 16 + lrow;
                int line = row >> 1;
                uint32_t u = (uint32_t)((((row & 1) << 2) + c) ^ (line & 7));
                ldsm4(bq[pr], bbase + line * 128u + u * 16u);
            }
            #pragma unroll
            for (int mt = 0; mt < 4; mt++)
                #pragma unroll
                for (int nt = 0; nt < 4; nt++) {
                    int pr = nt >> 1, hi = nt & 1;
                    mma16(acc[mt][nt], af[mt][0], af[mt][1], af[mt][2], af[mt][3],
                          bq[pr][hi], bq[pr][hi + 2]);
                }
        }
        p = (p + 1) & 3;
    }

    if (MODE != 3) {
        #pragma unroll
        for (int mt = 0; mt < 4; mt++) {
            #pragma unroll
            for (int nt = 0; nt < 4; nt++) {
                int n = n0 + wn * 32 + nt * 8 + cg * 2;
                float2 b2 = *(const float2*)(bias + n);
                #pragma unroll
                for (int h = 0; h < 2; h++) {
                    long r = m0 + wm * 64 + mt * 16 + h * 8 + gr;
                    float v0 = acc[mt][nt][h * 2 + 0] + b2.x;
                    float v1 = acc[mt][nt][h * 2 + 1] + b2.y;
                    if (MODE == 1) {
                        v0 = 0.5f * v0 * (1.f + erff(v0 * 0.70710678118654752f));
                        v1 = 0.5f * v1 * (1.f + erff(v1 * 0.70710678118654752f));
                    }
                    if (MODE == 2) {
                        float2 rr = unpack2(*(const uint32_t*)(res + r * N + n));
                        v0 += rr.x; v1 += rr.y;
                    }
                    *(uint32_t*)((__half*)outp + r * N + n) = pack2(v0, v1);
                }
            }
        }
    } else {
        // transpose through smem -> coalesced NCHW scatter
        float* out = (float*)outp;
        __syncthreads();
        float* T = (float*)sm;    // [128][66] floats = 33792B
        #pragma unroll
        for (int chunk = 0; chunk < 2; chunk++) {
            if ((wn >> 1) == chunk) {
                #pragma unroll
                for (int mt = 0; mt < 4; mt++) {
                    #pragma unroll
                    for (int nt = 0; nt < 4; nt++) {
                        int cl = (wn & 1) * 32 + nt * 8 + cg * 2;
                        int n  = n0 + chunk * 64 + cl;
                        float2 b2 = *(const float2*)(bias + n);
                        #pragma unroll
                        for (int h = 0; h < 2; h++) {
                            int rl = wm * 64 + mt * 16 + h * 8 + gr;
                            long r = m0 + rl;
                            float2 rr = unpack2(*(const uint32_t*)(res + r * 384 + n));
                            T[rl * 66 + cl]     = acc[mt][nt][h * 2 + 0] + b2.x + rr.x;
                            T[rl * 66 + cl + 1] = acc[mt][nt][h * 2 + 1] + b2.y + rr.y;
                        }
                    }
                }
            }
            __syncthreads();
            int ch = tid & 63;
            for (int g = tid >> 6; g < 16; g += 4) {
                long m = m0 + g * 8;
                int winI = (int)(m >> 6), sI = (int)(m & 63);
                int bI = winI >> 8, whI = (winI >> 4) & 15, wwI = winI & 15;
                int n = n0 + chunk * 64 + ch;
                long base = ((long)(bI * 384 + n)) * 16384
                          + (long)(whI * 8 + (sI >> 3)) * 128 + wwI * 8;
                float v[8];
                #pragma unroll
                for (int i = 0; i < 8; i++) v[i] = T[(g * 8 + i) * 66 + ch];
                *(float4*)(out + base)     = make_float4(v[0], v[1], v[2], v[3]);
                *(float4*)(out + base + 4) = make_float4(v[4], v[5], v[6], v[7]);
            }
            __syncthreads();
        }
    }
}

// ===========================================================================
// Kernel 3: tensor-core attention per (window, head). 128 threads, 4 warps.
// ===========================================================================
__global__ void __launch_bounds__(128) attn_kernel(
    const __half* __restrict__ QKV, __half* __restrict__ O)
{
    __shared__ __half qs[64 * 50];
    __shared__ __half ks[64 * 50];
    __shared__ __half vt[48 * 66];

    int head = blockIdx.x;
    long tok0 = (long)blockIdx.y * 64;
    int tid = threadIdx.x;
    int lane = tid & 31, wrp = tid >> 5;
    const __half* base = QKV + tok0 * 1152 + head * 48;

    for (int i = tid; i < 64 * 24; i += 128) {
        int t = i / 24, f2 = i % 24;
        *(uint32_t*)&qs[t * 50 + f2 * 2] =
            *(const uint32_t*)(base + (long)t * 1152 + f2 * 2);
        *(uint32_t*)&ks[t * 50 + f2 * 2] =
            *(const uint32_t*)(base + 384 + (long)t * 1152 + f2 * 2);
        uint32_t w = *(const uint32_t*)(base + 768 + (long)t * 1152 + f2 * 2);
        __half2 h = *(__half2*)&w;
        vt[(f2 * 2) * 66 + t]     = __low2half(h);
        vt[(f2 * 2 + 1) * 66 + t] = __high2half(h);
    }
    __syncthreads();

    int gr = lane >> 2, cg = lane & 3;
    int m0 = wrp * 16;

    float sacc[8][4];
    #pragma unroll
    for (int nt = 0; nt < 8; nt++)
        #pragma unroll
        for (int j = 0; j < 4; j++) sacc[nt][j] = 0.f;

    #pragma unroll
    for (int kc = 0; kc < 3; kc++) {
        uint32_t a0 = *(uint32_t*)&qs[(m0 + gr) * 50 + kc * 16 + cg * 2];
        uint32_t a1 = *(uint32_t*)&qs[(m0 + gr + 8) * 50 + kc * 16 + cg * 2];
        uint32_t a2 = *(uint32_t*)&qs[(m0 + gr) * 50 + kc * 16 + 8 + cg * 2];
        uint32_t a3 = *(uint32_t*)&qs[(m0 + gr + 8) * 50 + kc * 16 + 8 + cg * 2];
        #pragma unroll
        for (int nt = 0; nt < 8; nt++) {
            uint32_t b0 = *(uint32_t*)&ks[(nt * 8 + gr) * 50 + kc * 16 + cg * 2];
            uint32_t b1 = *(uint32_t*)&ks[(nt * 8 + gr) * 50 + kc * 16 + 8 + cg * 2];
            mma16(sacc[nt], a0, a1, a2, a3, b0, b1);
        }
    }

    const float scale = 0.14433756729740645f;
    float mx0 = -1e30f, mx1 = -1e30f;
    #pragma unroll
    for (int nt = 0; nt < 8; nt++) {
        mx0 = fmaxf(mx0, fmaxf(sacc[nt][0], sacc[nt][1]));
        mx1 = fmaxf(mx1, fmaxf(sacc[nt][2], sacc[nt][3]));
    }
    mx0 = fmaxf(mx0, __shfl_xor_sync(~0u, mx0, 1));
    mx0 = fmaxf(mx0, __shfl_xor_sync(~0u, mx0, 2));
    mx1 = fmaxf(mx1, __shfl_xor_sync(~0u, mx1, 1));
    mx1 = fmaxf(mx1, __shfl_xor_sync(~0u, mx1, 2));
    mx0 *= scale; mx1 *= scale;

    float e[8][4];
    float sum0 = 0.f, sum1 = 0.f;
    #pragma unroll
    for (int nt = 0; nt < 8; nt++) {
        e[nt][0] = __expf(sacc[nt][0] * scale - mx0);
        e[nt][1] = __expf(sacc[nt][1] * scale - mx0);
        e[nt][2] = __expf(sacc[nt][2] * scale - mx1);
        e[nt][3] = __expf(sacc[nt][3] * scale - mx1);
        sum0 += e[nt][0] + e[nt][1];
        sum1 += e[nt][2] + e[nt][3];
    }
    sum0 += __shfl_xor_sync(~0u, sum0, 1);
    sum0 += __shfl_xor_sync(~0u, sum0, 2);
    sum1 += __shfl_xor_sync(~0u, sum1, 1);
    sum1 += __shfl_xor_sync(~0u, sum1, 2);
    float inv0 = 1.f / sum0, inv1 = 1.f / sum1;

    uint32_t p0[8], p1[8];
    #pragma unroll
    for (int nt = 0; nt < 8; nt++) {
        p0[nt] = pack2(e[nt][0] * inv0, e[nt][1] * inv0);
        p1[nt] = pack2(e[nt][2] * inv1, e[nt][3] * inv1);
    }

    float oacc[6][4];
    #pragma unroll
    for (int nt = 0; nt < 6; nt++)
        #pragma unroll
        for (int j = 0; j < 4; j++) oacc[nt][j] = 0.f;

    #pragma unroll
    for (int kc = 0; kc < 4; kc++) {
        uint32_t a0 = p0[2 * kc],     a1 = p1[2 * kc];
        uint32_t a2 = p0[2 * kc + 1], a3 = p1[2 * kc + 1];
        #pragma unroll
        for (int nt = 0; nt < 6; nt++) {
            uint32_t b0 = *(uint32_t*)&vt[(nt * 8 + gr) * 66 + kc * 16 + cg * 2];
            uint32_t b1 = *(uint32_t*)&vt[(nt * 8 + gr) * 66 + kc * 16 + 8 + cg * 2];
            mma16(oacc[nt], a0, a1, a2, a3, b0, b1);
        }
    }

    #pragma unroll
    for (int nt = 0; nt < 6; nt++) {
        long col = head * 48 + nt * 8 + cg * 2;
        *(uint32_t*)(O + (tok0 + m0 + gr) * 384 + col)     = pack2(oacc[nt][0], oacc[nt][1]);
        *(uint32_t*)(O + (tok0 + m0 + gr + 8) * 384 + col) = pack2(oacc[nt][2], oacc[nt][3]);
    }
}

// ===========================================================================
// Kernel 5: LayerNorm2. fp16 in, fp16 out.
// ===========================================================================
__global__ void __launch_bounds__(128) ln2_kernel(
    const __half* __restrict__ Hh,
    const float* __restrict__ gw, const float* __restrict__ gb,
    __half* __restrict__ Y2)
{
    long t = blockIdx.x;
    int tid = threadIdx.x;
    const __half* row = Hh + t * 384;
    float v[3];
    float sum = 0.f, sq = 0.f;
    #pragma unroll
    for (int i = 0; i < 3; i++) {
        v[i] = __half2float(row[tid + i * 128]);
        sum += v[i]; sq += v[i] * v[i];
    }
    __shared__ float ssum[4], ssq[4];
    #pragma unroll
    for (int o = 16; o; o >>= 1) {
        sum += __shfl_xor_sync(~0u, sum, o);
        sq  += __shfl_xor_sync(~0u, sq,  o);
    }
    if ((tid & 31) == 0) { ssum[tid >> 5] = sum; ssq[tid >> 5] = sq; }
    __syncthreads();
    sum = ssum[0] + ssum[1] + ssum[2] + ssum[3];
    sq  = ssq[0]  + ssq[1]  + ssq[2]  + ssq[3];
    float m  = sum * (1.f / 384.f);
    float rs = rsqrtf(sq * (1.f / 384.f) - m * m + 1e-5f);
    #pragma unroll
    for (int i = 0; i < 3; i++) {
        int c = tid + i * 128;
        Y2[t * 384 + c] = __float2half((v[i] - m) * rs * gw[c] + gb[c]);
    }
}

// ===========================================================================
extern "C" void kernel_launch(void* const* d_in, const int* in_sizes, int n_in,
                              void* d_out, int out_size)
{
    const float* x     = (const float*)d_in[0];
    const float* n1_w  = (const float*)d_in[1];
    const float* n1_b  = (const float*)d_in[2];
    const float* in_w  = (const float*)d_in[3];
    const float* in_b  = (const float*)d_in[4];
    const float* out_w = (const float*)d_in[5];
    const float* out_b = (const float*)d_in[6];
    const float* n2_w  = (const float*)d_in[7];
    const float* n2_b  = (const float*)d_in[8];
    const float* w1    = (const float*)d_in[9];
    const float* b1    = (const float*)d_in[10];
    const float* w2    = (const float*)d_in[11];
    const float* b2    = (const float*)d_in[12];
    float* out = (float*)d_out;

    __half *WINh, *Yh, *Hb, *Wh;
    cudaGetSymbolAddress((void**)&WINh, g_hR);
    cudaGetSymbolAddress((void**)&Yh,   g_hA);
    cudaGetSymbolAddress((void**)&Hb,   g_hB);
    cudaGetSymbolAddress((void**)&Wh,   g_wh);

    __half* QKVh = Hb;                      // lifetime: steps 2-3
    __half* Oh   = Yh;                      // alias: Y dead after QKV gemm
    __half* H    = WINh;                    // in-place residual (elementwise)
    __half* Y2h  = Hb;                      // lifetime: steps 5-6 (QKV dead)
    __half* Gh   = Hb + (size_t)TOKS * 384;

    cudaFuncSetAttribute(mma_gemm<0>, cudaFuncAttributeMaxDynamicSharedMemorySize, GEMM_SMEM);
    cudaFuncSetAttribute(mma_gemm<1>, cudaFuncAttributeMaxDynamicSharedMemorySize, GEMM_SMEM);
    cudaFuncSetAttribute(mma_gemm<2>, cudaFuncAttributeMaxDynamicSharedMemorySize, GEMM_SMEM);
    cudaFuncSetAttribute(mma_gemm<3>, cudaFuncAttributeMaxDynamicSharedMemorySize, GEMM_SMEM);

    // 0. convert all weights to fp16 (one launch)
    cvt_all_kernel<<<4608, 256>>>(in_w, out_w, w1, w2, Wh);
    // 1. gather + LN1
    ln1_gather_kernel<<<2048 * 4, 256>>>(x, n1_w, n1_b, Yh, WINh);
    // 2. QKV projection (fp16 in/out)
    mma_gemm<0><<<dim3(1152 / 128, TOKS / 128), 256, GEMM_SMEM>>>(Yh, Wh + WQKV_OFF, in_b, nullptr, QKVh, 384, 1152);
    // 3. tensor-core attention (fp16 O out)
    attn_kernel<<<dim3(8, 2048), 128>>>(QKVh, Oh);
    // 4. out projection + residual -> H (fp16)
    mma_gemm<2><<<dim3(384 / 128, TOKS / 128), 256, GEMM_SMEM>>>(Oh, Wh + WO_OFF, out_b, WINh, H, 384, 384);
    // 5. LN2 (fp16 in/out)
    ln2_kernel<<<TOKS, 128>>>(H, n2_w, n2_b, Y2h);
    // 6. MLP fc1 + gelu (fp16 out)
    mma_gemm<1><<<dim3(768 / 128, TOKS / 128), 256, GEMM_SMEM>>>(Y2h, Wh + W1_OFF, b1, nullptr, Gh, 384, 768);
    // 7. MLP fc2 + residual + window-reverse scatter (fp32 out)
    mma_gemm<3><<<dim3(384 / 128, TOKS / 128), 256, GEMM_SMEM>>>(Gh, Wh + W2_OFF, b2, H, out, 768, 384);
}

// round 7
// speedup vs baseline: 5.1294x; 1.0967x over previous
#include <cuda_runtime.h>
#include <cuda_fp16.h>
#include <math.h>
#include <stdint.h>

#define TOKS 131072          // 2048 windows * 64 tokens

// fp16 scratch
__device__ __half g_hR[(size_t)TOKS * 384];      // WIN, later H (residual, fp16)
__device__ __half g_hA[(size_t)TOKS * 384];      // Y (post-LN1), later O (attn out)
__device__ __half g_hB[(size_t)TOKS * 1152];     // QKV, later Y2 (384) + G (768)
__device__ __half g_wh[1179648];                 // weights converted to half

#define WQKV_OFF 0
#define WO_OFF   442368
#define W1_OFF   589824
#define W2_OFF   884736

#define GEMM_SMEM 65536

// ===========================================================================
// helpers
// ===========================================================================
__device__ __forceinline__ void cp16(uint32_t dst, const void* src) {
    asm volatile("cp.async.cg.shared.global [%0], [%1], 16;"
        :: "r"(dst), "l"(src));
}
__device__ __forceinline__ void mma16(float* d, uint32_t a0, uint32_t a1,
                                      uint32_t a2, uint32_t a3,
                                      uint32_t b0, uint32_t b1) {
    asm volatile(
        "mma.sync.aligned.m16n8k16.row.col.f32.f16.f16.f32 "
        "{%0,%1,%2,%3}, {%4,%5,%6,%7}, {%8,%9}, {%0,%1,%2,%3};"
        : "+f"(d[0]), "+f"(d[1]), "+f"(d[2]), "+f"(d[3])
        : "r"(a0), "r"(a1), "r"(a2), "r"(a3), "r"(b0), "r"(b1));
}
__device__ __forceinline__ void ldsm4(uint32_t* r, uint32_t addr) {
    asm volatile("ldmatrix.sync.aligned.m8n8.x4.shared.b16 {%0,%1,%2,%3}, [%4];"
        : "=r"(r[0]), "=r"(r[1]), "=r"(r[2]), "=r"(r[3]) : "r"(addr));
}
__device__ __forceinline__ void ldsm4t(uint32_t* r, uint32_t addr) {
    asm volatile("ldmatrix.sync.aligned.m8n8.x4.trans.shared.b16 {%0,%1,%2,%3}, [%4];"
        : "=r"(r[0]), "=r"(r[1]), "=r"(r[2]), "=r"(r[3]) : "r"(addr));
}
__device__ __forceinline__ uint32_t pack2(float a, float b) {
    __half2 h = __floats2half2_rn(a, b);
    return *(uint32_t*)&h;
}
__device__ __forceinline__ float2 unpack2(uint32_t u) {
    return __half22float2(*(__half2*)&u);
}

// ===========================================================================
// Kernel 0: all weights fp32 -> fp16 in one launch
// ===========================================================================
__global__ void __launch_bounds__(256) cvt_all_kernel(
    const float* __restrict__ a, const float* __restrict__ b,
    const float* __restrict__ c, const float* __restrict__ d,
    __half* __restrict__ o)
{
    int i = blockIdx.x * 256 + threadIdx.x;
    if (i < 442368)       o[i] = __float2half(a[i]);
    else if (i < 589824)  o[i] = __float2half(b[i - 442368]);
    else if (i < 884736)  o[i] = __float2half(c[i - 589824]);
    else if (i < 1179648) o[i] = __float2half(d[i - 884736]);
}

// ===========================================================================
// Kernel 1: window gather + LayerNorm1. WIN fp16, Y fp16.
// ===========================================================================
__global__ void __launch_bounds__(256) ln1_gather_kernel(
    const float* __restrict__ x,
    const float* __restrict__ gw, const float* __restrict__ gb,
    __half* __restrict__ Y, __half* __restrict__ WIN)
{
    __shared__ float tile[384][17];
    __shared__ float s_mu[16], s_rs[16];

    int blk  = blockIdx.x;
    int win  = blk >> 2;
    int part = blk & 3;
    int b  = win >> 8;
    int wh = (win >> 4) & 15;
    int ww = win & 15;

    int tid = threadIdx.x;
    int sl  = tid & 15;
    int s   = part * 16 + sl;
    int r   = s >> 3, cw = s & 7;
    long xbase = (long)b * 384 * 16384 + (long)(wh * 8 + r) * 128 + ww * 8 + cw;

    for (int c = tid >> 4; c < 384; c += 16)
        tile[c][sl] = x[xbase + (long)c * 16384];
    __syncthreads();

    int lane = tid & 31, wd = tid >> 5;
    for (int t = wd * 2; t < wd * 2 + 2; t++) {
        float sum = 0.f, sq = 0.f;
        for (int c = lane; c < 384; c += 32) {
            float v = tile[c][t];
            sum += v; sq += v * v;
        }
        #pragma unroll
        for (int o = 16; o; o >>= 1) {
            sum += __shfl_xor_sync(~0u, sum, o);
            sq  += __shfl_xor_sync(~0u, sq,  o);
        }
        if (lane == 0) {
            float m = sum * (1.f / 384.f);
            float var = sq * (1.f / 384.f) - m * m;
            s_mu[t] = m;
            s_rs[t] = rsqrtf(var + 1e-5f);
        }
    }
    __syncthreads();

    long tok0 = (long)win * 64 + part * 16;
    for (int idx = tid; idx < 16 * 384; idx += 256) {
        int c = idx % 384, t = idx / 384;
        float v = tile[c][t];
        long o = (tok0 + t) * 384 + c;
        WIN[o] = __float2half(v);
        Y[o] = __float2half((v - s_mu[t]) * s_rs[t] * gw[c] + gb[c]);
    }
}

// ===========================================================================
// FP16 tensor-core GEMM, compile-time K. BM=128, BN=128, BK=32, 4-stage
// cp.async, 256 threads, ldmatrix + swizzle. Fully unrolled mainloop.
//  MODE 0: + bias, fp16 out             (QKV)
//  MODE 1: + bias, exact gelu, fp16 out (MLP1 -> G)
//  MODE 2: + bias + res(fp16), fp16 out (attn out proj -> H)
//  MODE 3: + bias + res(fp16), fp32 window-reverse scatter to NCHW (MLP2)
// ===========================================================================
template<int MODE, int K>
__global__ void __launch_bounds__(256, 2) mma_gemm(
    const __half* __restrict__ A, const __half* __restrict__ W,
    const float* __restrict__ bias, const __half* __restrict__ res,
    void* __restrict__ outp, int N)
{
    extern __shared__ uint32_t sm[];

    const int tid  = threadIdx.x;
    const int lane = tid & 31, wid = tid >> 5;
    const int wm = wid & 1;
    const int wn = wid >> 1;
    const int gr = lane >> 2;
    const int cg = lane & 3;

    const long m0 = (long)blockIdx.y * 128;
    const int  n0 = blockIdx.x * 128;

    const uint32_t sb = (uint32_t)__cvta_generic_to_shared(sm);
    const __half* Ag = A + m0 * K;
    const __half* Wg = W + (long)n0 * K;

    float acc[4][4][4];
    #pragma unroll
    for (int i = 0; i < 4; i++)
        #pragma unroll
        for (int j = 0; j < 4; j++)
            #pragma unroll
            for (int k = 0; k < 4; k++) acc[i][j][k] = 0.f;

    constexpr int NS = K >> 5;

    auto issue = [&](int s, int p) {
        #pragma unroll
        for (int i = 0; i < 2; i++) {
            int idx = tid + i * 256;
            int row = idx >> 2, c = idx & 3;
            int line = row >> 1;
            uint32_t u = (uint32_t)((((row & 1) << 2) + c) ^ (line & 7));
            uint32_t off = p * 16384u + line * 128u + u * 16u;
            cp16(sb + off,          Ag + (long)row * K + s * 32 + c * 8);
            cp16(sb + 8192u + off,  Wg + (long)row * K + s * 32 + c * 8);
        }
        asm volatile("cp.async.commit_group;");
    };

    const int lrow = (lane & 7) + ((lane >> 3) & 1) * 8;
    const int lk   = lane >> 4;

    issue(0, 0);
    issue(1, 1);
    issue(2, 2);
    #pragma unroll
    for (int s = 0; s < NS; s++) {
        const int p = s & 3;
        if (s + 2 < NS)      asm volatile("cp.async.wait_group 2;");
        else if (s + 1 < NS) asm volatile("cp.async.wait_group 1;");
        else                 asm volatile("cp.async.wait_group 0;");
        __syncthreads();
        if (s + 3 < NS) issue(s + 3, (s + 3) & 3);

        const uint32_t abase = sb + p * 16384u;
        const uint32_t bbase = abase + 8192u;

        #pragma unroll
        for (int kc = 0; kc < 2; kc++) {
            int c = kc * 2 + lk;
            uint32_t af[4][4], bq[2][4];
            #pragma unroll
            for (int mt = 0; mt < 4; mt++) {
                int row = wm * 64 + mt * 16 + lrow;
                int line = row >> 1;
                uint32_t u = (uint32_t)((((row & 1) << 2) + c) ^ (line & 7));
                ldsm4(af[mt], abase + line * 128u + u * 16u);
            }
            #pragma unroll
            for (int pr = 0; pr < 2; pr++) {
                int row = wn * 32 + pr * 16 + lrow;
                int line = row >> 1;
                uint32_t u = (uint32_t)((((row & 1) << 2) + c) ^ (line & 7));
                ldsm4(bq[pr], bbase + line * 128u + u * 16u);
            }
            #pragma unroll
            for (int mt = 0; mt < 4; mt++)
                #pragma unroll
                for (int nt = 0; nt < 4; nt++) {
                    int pr = nt >> 1, hi = nt & 1;
                    mma16(acc[mt][nt], af[mt][0], af[mt][1], af[mt][2], af[mt][3],
                          bq[pr][hi], bq[pr][hi + 2]);
                }
        }
    }

    if (MODE != 3) {
        #pragma unroll
        for (int mt = 0; mt < 4; mt++) {
            #pragma unroll
            for (int nt = 0; nt < 4; nt++) {
                int n = n0 + wn * 32 + nt * 8 + cg * 2;
                float2 b2 = *(const float2*)(bias + n);
                #pragma unroll
                for (int h = 0; h < 2; h++) {
                    long r = m0 + wm * 64 + mt * 16 + h * 8 + gr;
                    float v0 = acc[mt][nt][h * 2 + 0] + b2.x;
                    float v1 = acc[mt][nt][h * 2 + 1] + b2.y;
                    if (MODE == 1) {
                        v0 = 0.5f * v0 * (1.f + erff(v0 * 0.70710678118654752f));
                        v1 = 0.5f * v1 * (1.f + erff(v1 * 0.70710678118654752f));
                    }
                    if (MODE == 2) {
                        float2 rr = unpack2(*(const uint32_t*)(res + r * N + n));
                        v0 += rr.x; v1 += rr.y;
                    }
                    *(uint32_t*)((__half*)outp + r * N + n) = pack2(v0, v1);
                }
            }
        }
    } else {
        float* out = (float*)outp;
        __syncthreads();
        float* T = (float*)sm;    // [128][66] floats
        #pragma unroll
        for (int chunk = 0; chunk < 2; chunk++) {
            if ((wn >> 1) == chunk) {
                #pragma unroll
                for (int mt = 0; mt < 4; mt++) {
                    #pragma unroll
                    for (int nt = 0; nt < 4; nt++) {
                        int cl = (wn & 1) * 32 + nt * 8 + cg * 2;
                        int n  = n0 + chunk * 64 + cl;
                        float2 b2 = *(const float2*)(bias + n);
                        #pragma unroll
                        for (int h = 0; h < 2; h++) {
                            int rl = wm * 64 + mt * 16 + h * 8 + gr;
                            long r = m0 + rl;
                            float2 rr = unpack2(*(const uint32_t*)(res + r * 384 + n));
                            T[rl * 66 + cl]     = acc[mt][nt][h * 2 + 0] + b2.x + rr.x;
                            T[rl * 66 + cl + 1] = acc[mt][nt][h * 2 + 1] + b2.y + rr.y;
                        }
                    }
                }
            }
            __syncthreads();
            int ch = tid & 63;
            for (int g = tid >> 6; g < 16; g += 4) {
                long m = m0 + g * 8;
                int winI = (int)(m >> 6), sI = (int)(m & 63);
                int bI = winI >> 8, whI = (winI >> 4) & 15, wwI = winI & 15;
                int n = n0 + chunk * 64 + ch;
                long base = ((long)(bI * 384 + n)) * 16384
                          + (long)(whI * 8 + (sI >> 3)) * 128 + wwI * 8;
                float v[8];
                #pragma unroll
                for (int i = 0; i < 8; i++) v[i] = T[(g * 8 + i) * 66 + ch];
                *(float4*)(out + base)     = make_float4(v[0], v[1], v[2], v[3]);
                *(float4*)(out + base + 4) = make_float4(v[4], v[5], v[6], v[7]);
            }
            __syncthreads();
        }
    }
}

// ===========================================================================
// Kernel 3: tensor-core attention per (window, head). 128 threads, 4 warps.
// Q/K/V in smem at 112B row stride (conflict-free LDSM). Fragments via
// ldmatrix.x4; V via ldmatrix.x4.trans (no transpose writes). Register
// softmax; P stays in registers for P@V.
// ===========================================================================
__global__ void __launch_bounds__(128) attn_kernel(
    const __half* __restrict__ QKV, __half* __restrict__ O)
{
    __shared__ __half qs[64 * 56];
    __shared__ __half ks[64 * 56];
    __shared__ __half vs[64 * 56];

    int head = blockIdx.x;
    long tok0 = (long)blockIdx.y * 64;
    int tid = threadIdx.x;
    int lane = tid & 31, wrp = tid >> 5;
    const __half* base = QKV + tok0 * 1152 + head * 48;

    for (int i = tid; i < 384; i += 128) {
        int t = i / 6, c = i % 6;
        long g = (long)t * 1152 + c * 8;
        *(uint4*)&qs[t * 56 + c * 8] = *(const uint4*)(base + g);
        *(uint4*)&ks[t * 56 + c * 8] = *(const uint4*)(base + 384 + g);
        *(uint4*)&vs[t * 56 + c * 8] = *(const uint4*)(base + 768 + g);
    }
    __syncthreads();

    const uint32_t sq = (uint32_t)__cvta_generic_to_shared(qs);
    const uint32_t sk = (uint32_t)__cvta_generic_to_shared(ks);
    const uint32_t sv = (uint32_t)__cvta_generic_to_shared(vs);

    int gr = lane >> 2, cg = lane & 3;
    int m0 = wrp * 16;

    // lane addressing components
    const int arow  = m0 + (lane & 7) + ((lane >> 3) & 1) * 8;   // Q rows
    const int acolb = (lane >> 4) * 16;
    const int krow  = (lane & 7) + ((lane >> 4) & 1) * 8;        // K rows (in 16-blk)
    const int kcolb = ((lane >> 3) & 1) * 16;
    const int vrow  = (lane & 7) + ((lane >> 3) & 1) * 8;        // V rows (in 16-blk)
    const int vsel  = lane >> 4;                                 // V nt select

    // --- S = Q K^T
    float sacc[8][4];
    #pragma unroll
    for (int nt = 0; nt < 8; nt++)
        #pragma unroll
        for (int j = 0; j < 4; j++) sacc[nt][j] = 0.f;

    #pragma unroll
    for (int kc = 0; kc < 3; kc++) {
        uint32_t a[4];
        ldsm4(a, sq + (uint32_t)(arow * 112 + kc * 32 + acolb));
        #pragma unroll
        for (int j = 0; j < 4; j++) {
            uint32_t b[4];
            ldsm4(b, sk + (uint32_t)((j * 16 + krow) * 112 + kc * 32 + kcolb));
            mma16(sacc[2 * j],     a[0], a[1], a[2], a[3], b[0], b[1]);
            mma16(sacc[2 * j + 1], a[0], a[1], a[2], a[3], b[2], b[3]);
        }
    }

    // --- register softmax (rows gr and gr+8), scale = 1/sqrt(48)
    const float scale = 0.14433756729740645f;
    float mx0 = -1e30f, mx1 = -1e30f;
    #pragma unroll
    for (int nt = 0; nt < 8; nt++) {
        mx0 = fmaxf(mx0, fmaxf(sacc[nt][0], sacc[nt][1]));
        mx1 = fmaxf(mx1, fmaxf(sacc[nt][2], sacc[nt][3]));
    }
    mx0 = fmaxf(mx0, __shfl_xor_sync(~0u, mx0, 1));
    mx0 = fmaxf(mx0, __shfl_xor_sync(~0u, mx0, 2));
    mx1 = fmaxf(mx1, __shfl_xor_sync(~0u, mx1, 1));
    mx1 = fmaxf(mx1, __shfl_xor_sync(~0u, mx1, 2));
    mx0 *= scale; mx1 *= scale;

    float e[8][4];
    float sum0 = 0.f, sum1 = 0.f;
    #pragma unroll
    for (int nt = 0; nt < 8; nt++) {
        e[nt][0] = __expf(sacc[nt][0] * scale - mx0);
        e[nt][1] = __expf(sacc[nt][1] * scale - mx0);
        e[nt][2] = __expf(sacc[nt][2] * scale - mx1);
        e[nt][3] = __expf(sacc[nt][3] * scale - mx1);
        sum0 += e[nt][0] + e[nt][1];
        sum1 += e[nt][2] + e[nt][3];
    }
    sum0 += __shfl_xor_sync(~0u, sum0, 1);
    sum0 += __shfl_xor_sync(~0u, sum0, 2);
    sum1 += __shfl_xor_sync(~0u, sum1, 1);
    sum1 += __shfl_xor_sync(~0u, sum1, 2);
    float inv0 = 1.f / sum0, inv1 = 1.f / sum1;

    uint32_t p0[8], p1[8];
    #pragma unroll
    for (int nt = 0; nt < 8; nt++) {
        p0[nt] = pack2(e[nt][0] * inv0, e[nt][1] * inv0);
        p1[nt] = pack2(e[nt][2] * inv1, e[nt][3] * inv1);
    }

    // --- O = P @ V : V fragments via ldmatrix.trans
    float oacc[6][4];
    #pragma unroll
    for (int nt = 0; nt < 6; nt++)
        #pragma unroll
        for (int j = 0; j < 4; j++) oacc[nt][j] = 0.f;

    #pragma unroll
    for (int kc = 0; kc < 4; kc++) {
        uint32_t a0 = p0[2 * kc],     a1 = p1[2 * kc];
        uint32_t a2 = p0[2 * kc + 1], a3 = p1[2 * kc + 1];
        #pragma unroll
        for (int j = 0; j < 3; j++) {
            uint32_t b[4];
            ldsm4t(b, sv + (uint32_t)((kc * 16 + vrow) * 112 + (2 * j + vsel) * 16));
            mma16(oacc[2 * j],     a0, a1, a2, a3, b[0], b[1]);
            mma16(oacc[2 * j + 1], a0, a1, a2, a3, b[2], b[3]);
        }
    }

    #pragma unroll
    for (int nt = 0; nt < 6; nt++) {
        long col = head * 48 + nt * 8 + cg * 2;
        *(uint32_t*)(O + (tok0 + m0 + gr) * 384 + col)     = pack2(oacc[nt][0], oacc[nt][1]);
        *(uint32_t*)(O + (tok0 + m0 + gr + 8) * 384 + col) = pack2(oacc[nt][2], oacc[nt][3]);
    }
}

// ===========================================================================
// Kernel 5: LayerNorm2. fp16 in, fp16 out.
// ===========================================================================
__global__ void __launch_bounds__(128) ln2_kernel(
    const __half* __restrict__ Hh,
    const float* __restrict__ gw, const float* __restrict__ gb,
    __half* __restrict__ Y2)
{
    long t = blockIdx.x;
    int tid = threadIdx.x;
    const __half* row = Hh + t * 384;
    float v[3];
    float sum = 0.f, sq = 0.f;
    #pragma unroll
    for (int i = 0; i < 3; i++) {
        v[i] = __half2float(row[tid + i * 128]);
        sum += v[i]; sq += v[i] * v[i];
    }
    __shared__ float ssum[4], ssq[4];
    #pragma unroll
    for (int o = 16; o; o >>= 1) {
        sum += __shfl_xor_sync(~0u, sum, o);
        sq  += __shfl_xor_sync(~0u, sq,  o);
    }
    if ((tid & 31) == 0) { ssum[tid >> 5] = sum; ssq[tid >> 5] = sq; }
    __syncthreads();
    sum = ssum[0] + ssum[1] + ssum[2] + ssum[3];
    sq  = ssq[0]  + ssq[1]  + ssq[2]  + ssq[3];
    float m  = sum * (1.f / 384.f);
    float rs = rsqrtf(sq * (1.f / 384.f) - m * m + 1e-5f);
    #pragma unroll
    for (int i = 0; i < 3; i++) {
        int c = tid + i * 128;
        Y2[t * 384 + c] = __float2half((v[i] - m) * rs * gw[c] + gb[c]);
    }
}

// ===========================================================================
extern "C" void kernel_launch(void* const* d_in, const int* in_sizes, int n_in,
                              void* d_out, int out_size)
{
    const float* x     = (const float*)d_in[0];
    const float* n1_w  = (const float*)d_in[1];
    const float* n1_b  = (const float*)d_in[2];
    const float* in_w  = (const float*)d_in[3];
    const float* in_b  = (const float*)d_in[4];
    const float* out_w = (const float*)d_in[5];
    const float* out_b = (const float*)d_in[6];
    const float* n2_w  = (const float*)d_in[7];
    const float* n2_b  = (const float*)d_in[8];
    const float* w1    = (const float*)d_in[9];
    const float* b1    = (const float*)d_in[10];
    const float* w2    = (const float*)d_in[11];
    const float* b2    = (const float*)d_in[12];
    float* out = (float*)d_out;

    __half *WINh, *Yh, *Hb, *Wh;
    cudaGetSymbolAddress((void**)&WINh, g_hR);
    cudaGetSymbolAddress((void**)&Yh,   g_hA);
    cudaGetSymbolAddress((void**)&Hb,   g_hB);
    cudaGetSymbolAddress((void**)&Wh,   g_wh);

    __half* QKVh = Hb;
    __half* Oh   = Yh;
    __half* H    = WINh;
    __half* Y2h  = Hb;
    __half* Gh   = Hb + (size_t)TOKS * 384;

    cudaFuncSetAttribute((const void*)mma_gemm<0,384>, cudaFuncAttributeMaxDynamicSharedMemorySize, GEMM_SMEM);
    cudaFuncSetAttribute((const void*)mma_gemm<1,384>, cudaFuncAttributeMaxDynamicSharedMemorySize, GEMM_SMEM);
    cudaFuncSetAttribute((const void*)mma_gemm<2,384>, cudaFuncAttributeMaxDynamicSharedMemorySize, GEMM_SMEM);
    cudaFuncSetAttribute((const void*)mma_gemm<3,768>, cudaFuncAttributeMaxDynamicSharedMemorySize, GEMM_SMEM);

    // 0. convert all weights to fp16
    cvt_all_kernel<<<4608, 256>>>(in_w, out_w, w1, w2, Wh);
    // 1. gather + LN1
    ln1_gather_kernel<<<2048 * 4, 256>>>(x, n1_w, n1_b, Yh, WINh);
    // 2. QKV projection
    mma_gemm<0,384><<<dim3(1152 / 128, TOKS / 128), 256, GEMM_SMEM>>>(Yh, Wh + WQKV_OFF, in_b, nullptr, QKVh, 1152);
    // 3. tensor-core attention
    attn_kernel<<<dim3(8, 2048), 128>>>(QKVh, Oh);
    // 4. out projection + residual -> H
    mma_gemm<2,384><<<dim3(384 / 128, TOKS / 128), 256, GEMM_SMEM>>>(Oh, Wh + WO_OFF, out_b, WINh, H, 384);
    // 5. LN2
    ln2_kernel<<<TOKS, 128>>>(H, n2_w, n2_b, Y2h);
    // 6. MLP fc1 + gelu
    mma_gemm<1,384><<<dim3(768 / 128, TOKS / 128), 256, GEMM_SMEM>>>(Y2h, Wh + W1_OFF, b1, nullptr, Gh, 768);
    // 7. MLP fc2 + residual + window-reverse scatter
    mma_gemm<3,768><<<dim3(384 / 128, TOKS / 128), 256, GEMM_SMEM>>>(Gh, Wh + W2_OFF, b2, H, out, 384);
}

// round 8
// speedup vs baseline: 5.1455x; 1.0031x over previous
#include <cuda_runtime.h>
#include <cuda_fp16.h>
#include <math.h>
#include <stdint.h>

#define TOKS 131072          // 2048 windows * 64 tokens

// fp16 scratch
__device__ __half g_hR[(size_t)TOKS * 384];      // WIN, later H (residual, fp16)
__device__ __half g_hA[(size_t)TOKS * 384];      // Y (post-LN1), later O (attn out)
__device__ __half g_hB[(size_t)TOKS * 1152];     // QKV, later Y2 (384) + G (768)
__device__ __half g_wh[1179648];                 // weights converted to half

#define WQKV_OFF 0
#define WO_OFF   442368
#define W1_OFF   589824
#define W2_OFF   884736

#define GEMM_SMEM 65536
#define ATTN_SMEM 148480     // 64 rows x 1160 halves (stride 2320B = 145 odd units)

// ===========================================================================
// helpers
// ===========================================================================
__device__ __forceinline__ void cp16(uint32_t dst, const void* src) {
    asm volatile("cp.async.cg.shared.global [%0], [%1], 16;"
        :: "r"(dst), "l"(src));
}
__device__ __forceinline__ void mma16(float* d, uint32_t a0, uint32_t a1,
                                      uint32_t a2, uint32_t a3,
                                      uint32_t b0, uint32_t b1) {
    asm volatile(
        "mma.sync.aligned.m16n8k16.row.col.f32.f16.f16.f32 "
        "{%0,%1,%2,%3}, {%4,%5,%6,%7}, {%8,%9}, {%0,%1,%2,%3};"
        : "+f"(d[0]), "+f"(d[1]), "+f"(d[2]), "+f"(d[3])
        : "r"(a0), "r"(a1), "r"(a2), "r"(a3), "r"(b0), "r"(b1));
}
__device__ __forceinline__ void ldsm4(uint32_t* r, uint32_t addr) {
    asm volatile("ldmatrix.sync.aligned.m8n8.x4.shared.b16 {%0,%1,%2,%3}, [%4];"
        : "=r"(r[0]), "=r"(r[1]), "=r"(r[2]), "=r"(r[3]) : "r"(addr));
}
__device__ __forceinline__ void ldsm4t(uint32_t* r, uint32_t addr) {
    asm volatile("ldmatrix.sync.aligned.m8n8.x4.trans.shared.b16 {%0,%1,%2,%3}, [%4];"
        : "=r"(r[0]), "=r"(r[1]), "=r"(r[2]), "=r"(r[3]) : "r"(addr));
}
__device__ __forceinline__ uint32_t pack2(float a, float b) {
    __half2 h = __floats2half2_rn(a, b);
    return *(uint32_t*)&h;
}
__device__ __forceinline__ float2 unpack2(uint32_t u) {
    return __half22float2(*(__half2*)&u);
}

// ===========================================================================
// Kernel 0: all weights fp32 -> fp16 in one launch
// ===========================================================================
__global__ void __launch_bounds__(256) cvt_all_kernel(
    const float* __restrict__ a, const float* __restrict__ b,
    const float* __restrict__ c, const float* __restrict__ d,
    __half* __restrict__ o)
{
    int i = blockIdx.x * 256 + threadIdx.x;
    if (i < 442368)       o[i] = __float2half(a[i]);
    else if (i < 589824)  o[i] = __float2half(b[i - 442368]);
    else if (i < 884736)  o[i] = __float2half(c[i - 589824]);
    else if (i < 1179648) o[i] = __float2half(d[i - 884736]);
}

// ===========================================================================
// Kernel 1: window gather + LayerNorm1. WIN fp16, Y fp16.
// ===========================================================================
__global__ void __launch_bounds__(256) ln1_gather_kernel(
    const float* __restrict__ x,
    const float* __restrict__ gw, const float* __restrict__ gb,
    __half* __restrict__ Y, __half* __restrict__ WIN)
{
    __shared__ float tile[384][17];
    __shared__ float s_mu[16], s_rs[16];

    int blk  = blockIdx.x;
    int win  = blk >> 2;
    int part = blk & 3;
    int b  = win >> 8;
    int wh = (win >> 4) & 15;
    int ww = win & 15;

    int tid = threadIdx.x;
    int sl  = tid & 15;
    int s   = part * 16 + sl;
    int r   = s >> 3, cw = s & 7;
    long xbase = (long)b * 384 * 16384 + (long)(wh * 8 + r) * 128 + ww * 8 + cw;

    for (int c = tid >> 4; c < 384; c += 16)
        tile[c][sl] = x[xbase + (long)c * 16384];
    __syncthreads();

    int lane = tid & 31, wd = tid >> 5;
    for (int t = wd * 2; t < wd * 2 + 2; t++) {
        float sum = 0.f, sq = 0.f;
        for (int c = lane; c < 384; c += 32) {
            float v = tile[c][t];
            sum += v; sq += v * v;
        }
        #pragma unroll
        for (int o = 16; o; o >>= 1) {
            sum += __shfl_xor_sync(~0u, sum, o);
            sq  += __shfl_xor_sync(~0u, sq,  o);
        }
        if (lane == 0) {
            float m = sum * (1.f / 384.f);
            float var = sq * (1.f / 384.f) - m * m;
            s_mu[t] = m;
            s_rs[t] = rsqrtf(var + 1e-5f);
        }
    }
    __syncthreads();

    long tok0 = (long)win * 64 + part * 16;
    for (int idx = tid; idx < 16 * 384; idx += 256) {
        int c = idx % 384, t = idx / 384;
        float v = tile[c][t];
        long o = (tok0 + t) * 384 + c;
        WIN[o] = __float2half(v);
        Y[o] = __float2half((v - s_mu[t]) * s_rs[t] * gw[c] + gb[c]);
    }
}

// ===========================================================================
// FP16 tensor-core GEMM, compile-time K. BM=128, BN=128, BK=32, 4-stage
// cp.async, 256 threads, ldmatrix + swizzle. Fully unrolled mainloop.
// ===========================================================================
template<int MODE, int K>
__global__ void __launch_bounds__(256, 2) mma_gemm(
    const __half* __restrict__ A, const __half* __restrict__ W,
    const float* __restrict__ bias, const __half* __restrict__ res,
    void* __restrict__ outp, int N)
{
    extern __shared__ uint32_t sm[];

    const int tid  = threadIdx.x;
    const int lane = tid & 31, wid = tid >> 5;
    const int wm = wid & 1;
    const int wn = wid >> 1;
    const int gr = lane >> 2;
    const int cg = lane & 3;

    const long m0 = (long)blockIdx.y * 128;
    const int  n0 = blockIdx.x * 128;

    const uint32_t sb = (uint32_t)__cvta_generic_to_shared(sm);
    const __half* Ag = A + m0 * K;
    const __half* Wg = W + (long)n0 * K;

    float acc[4][4][4];
    #pragma unroll
    for (int i = 0; i < 4; i++)
        #pragma unroll
        for (int j = 0; j < 4; j++)
            #pragma unroll
            for (int k = 0; k < 4; k++) acc[i][j][k] = 0.f;

    constexpr int NS = K >> 5;

    auto issue = [&](int s, int p) {
        #pragma unroll
        for (int i = 0; i < 2; i++) {
            int idx = tid + i * 256;
            int row = idx >> 2, c = idx & 3;
            int line = row >> 1;
            uint32_t u = (uint32_t)((((row & 1) << 2) + c) ^ (line & 7));
            uint32_t off = p * 16384u + line * 128u + u * 16u;
            cp16(sb + off,          Ag + (long)row * K + s * 32 + c * 8);
            cp16(sb + 8192u + off,  Wg + (long)row * K + s * 32 + c * 8);
        }
        asm volatile("cp.async.commit_group;");
    };

    const int lrow = (lane & 7) + ((lane >> 3) & 1) * 8;
    const int lk   = lane >> 4;

    issue(0, 0);
    issue(1, 1);
    issue(2, 2);
    #pragma unroll
    for (int s = 0; s < NS; s++) {
        const int p = s & 3;
        if (s + 2 < NS)      asm volatile("cp.async.wait_group 2;");
        else if (s + 1 < NS) asm volatile("cp.async.wait_group 1;");
        else                 asm volatile("cp.async.wait_group 0;");
        __syncthreads();
        if (s + 3 < NS) issue(s + 3, (s + 3) & 3);

        const uint32_t abase = sb + p * 16384u;
        const uint32_t bbase = abase + 8192u;

        #pragma unroll
        for (int kc = 0; kc < 2; kc++) {
            int c = kc * 2 + lk;
            uint32_t af[4][4], bq[2][4];
            #pragma unroll
            for (int mt = 0; mt < 4; mt++) {
                int row = wm * 64 + mt * 16 + lrow;
                int line = row >> 1;
                uint32_t u = (uint32_t)((((row & 1) << 2) + c) ^ (line & 7));
                ldsm4(af[mt], abase + line * 128u + u * 16u);
            }
            #pragma unroll
            for (int pr = 0; pr < 2; pr++) {
                int row = wn * 32 + pr * 16 + lrow;
                int line = row >> 1;
                uint32_t u = (uint32_t)((((row & 1) << 2) + c) ^ (line & 7));
                ldsm4(bq[pr], bbase + line * 128u + u * 16u);
            }
            #pragma unroll
            for (int mt = 0; mt < 4; mt++)
                #pragma unroll
                for (int nt = 0; nt < 4; nt++) {
                    int pr = nt >> 1, hi = nt & 1;
                    mma16(acc[mt][nt], af[mt][0], af[mt][1], af[mt][2], af[mt][3],
                          bq[pr][hi], bq[pr][hi + 2]);
                }
        }
    }

    if (MODE != 3) {
        #pragma unroll
        for (int mt = 0; mt < 4; mt++) {
            #pragma unroll
            for (int nt = 0; nt < 4; nt++) {
                int n = n0 + wn * 32 + nt * 8 + cg * 2;
                float2 b2 = *(const float2*)(bias + n);
                #pragma unroll
                for (int h = 0; h < 2; h++) {
                    long r = m0 + wm * 64 + mt * 16 + h * 8 + gr;
                    float v0 = acc[mt][nt][h * 2 + 0] + b2.x;
                    float v1 = acc[mt][nt][h * 2 + 1] + b2.y;
                    if (MODE == 1) {
                        v0 = 0.5f * v0 * (1.f + erff(v0 * 0.70710678118654752f));
                        v1 = 0.5f * v1 * (1.f + erff(v1 * 0.70710678118654752f));
                    }
                    if (MODE == 2) {
                        float2 rr = unpack2(*(const uint32_t*)(res + r * N + n));
                        v0 += rr.x; v1 += rr.y;
                    }
                    *(uint32_t*)((__half*)outp + r * N + n) = pack2(v0, v1);
                }
            }
        }
    } else {
        float* out = (float*)outp;
        __syncthreads();
        float* T = (float*)sm;    // [128][66] floats
        #pragma unroll
        for (int chunk = 0; chunk < 2; chunk++) {
            if ((wn >> 1) == chunk) {
                #pragma unroll
                for (int mt = 0; mt < 4; mt++) {
                    #pragma unroll
                    for (int nt = 0; nt < 4; nt++) {
                        int cl = (wn & 1) * 32 + nt * 8 + cg * 2;
                        int n  = n0 + chunk * 64 + cl;
                        float2 b2 = *(const float2*)(bias + n);
                        #pragma unroll
                        for (int h = 0; h < 2; h++) {
                            int rl = wm * 64 + mt * 16 + h * 8 + gr;
                            long r = m0 + rl;
                            float2 rr = unpack2(*(const uint32_t*)(res + r * 384 + n));
                            T[rl * 66 + cl]     = acc[mt][nt][h * 2 + 0] + b2.x + rr.x;
                            T[rl * 66 + cl + 1] = acc[mt][nt][h * 2 + 1] + b2.y + rr.y;
                        }
                    }
                }
            }
            __syncthreads();
            int ch = tid & 63;
            for (int g = tid >> 6; g < 16; g += 4) {
                long m = m0 + g * 8;
                int winI = (int)(m >> 6), sI = (int)(m & 63);
                int bI = winI >> 8, whI = (winI >> 4) & 15, wwI = winI & 15;
                int n = n0 + chunk * 64 + ch;
                long base = ((long)(bI * 384 + n)) * 16384
                          + (long)(whI * 8 + (sI >> 3)) * 128 + wwI * 8;
                float v[8];
                #pragma unroll
                for (int i = 0; i < 8; i++) v[i] = T[(g * 8 + i) * 66 + ch];
                *(float4*)(out + base)     = make_float4(v[0], v[1], v[2], v[3]);
                *(float4*)(out + base + 4) = make_float4(v[4], v[5], v[6], v[7]);
            }
            __syncthreads();
        }
    }
}

// ===========================================================================
// Kernel 3: merged-window tensor-core attention. One block per WINDOW,
// 512 threads (16 warps). QKV for the window staged ONCE in smem
// (row stride 1160 halves = 145 x 16B, odd -> conflict-free ldmatrix).
// Warp (head, half): head = wid>>1 owns cols head*48.., half = wid&1 owns
// rows half*32..+31 (2 m16 tiles). Identical math to previous version.
// ===========================================================================
__global__ void __launch_bounds__(512) attn_kernel(
    const __half* __restrict__ QKV, __half* __restrict__ O)
{
    extern __shared__ __half qkv[];   // [64][1160]
    const int STRB = 2320;            // row stride in bytes

    int win = blockIdx.x;
    long tok0 = (long)win * 64;
    int tid = threadIdx.x;
    int lane = tid & 31, wid = tid >> 5;
    const __half* g = QKV + tok0 * 1152;

    // coalesced load: each warp loads 4 rows, lanes stride 16B chunks
    for (int t = wid; t < 64; t += 16) {
        const __half* gr_ = g + (long)t * 1152;
        __half* sr = qkv + t * 1160;
        #pragma unroll
        for (int c = lane; c < 144; c += 32)
            *(uint4*)(sr + c * 8) = *(const uint4*)(gr_ + c * 8);
    }
    __syncthreads();

    const uint32_t sb = (uint32_t)__cvta_generic_to_shared(qkv);
    const int head = wid >> 1;
    const int m0   = (wid & 1) * 32;
    const int gr   = lane >> 2, cg = lane & 3;

    const int qoffB = head * 96;
    const int koffB = 768 + head * 96;
    const int voffB = 1536 + head * 96;

    const int lrow = (lane & 7) + ((lane >> 3) & 1) * 8;   // A rows
    const int lkA  = lane >> 4;                            // A col half
    const int krow = (lane & 7) + ((lane >> 4) & 1) * 8;   // K rows
    const int kcolb= ((lane >> 3) & 1) * 16;
    const int vrow = (lane & 7) + ((lane >> 3) & 1) * 8;   // V rows
    const int vsel = lane >> 4;

    // --- S = Q K^T : 2 m-tiles x 8 n-tiles
    float sacc[2][8][4];
    #pragma unroll
    for (int mt = 0; mt < 2; mt++)
        #pragma unroll
        for (int nt = 0; nt < 8; nt++)
            #pragma unroll
            for (int j = 0; j < 4; j++) sacc[mt][nt][j] = 0.f;

    #pragma unroll
    for (int kc = 0; kc < 3; kc++) {
        uint32_t a[2][4];
        #pragma unroll
        for (int mt = 0; mt < 2; mt++)
            ldsm4(a[mt], sb + (uint32_t)((m0 + mt * 16 + lrow) * STRB
                                         + qoffB + kc * 32 + lkA * 16));
        #pragma unroll
        for (int j = 0; j < 4; j++) {
            uint32_t b[4];
            ldsm4(b, sb + (uint32_t)((j * 16 + krow) * STRB
                                     + koffB + kc * 32 + kcolb));
            #pragma unroll
            for (int mt = 0; mt < 2; mt++) {
                mma16(sacc[mt][2 * j],     a[mt][0], a[mt][1], a[mt][2], a[mt][3], b[0], b[1]);
                mma16(sacc[mt][2 * j + 1], a[mt][0], a[mt][1], a[mt][2], a[mt][3], b[2], b[3]);
            }
        }
    }

    // --- register softmax per m-tile (rows gr and gr+8)
    const float scale = 0.14433756729740645f;   // 1/sqrt(48)
    uint32_t p0[2][8], p1[2][8];
    #pragma unroll
    for (int mt = 0; mt < 2; mt++) {
        float mx0 = -1e30f, mx1 = -1e30f;
        #pragma unroll
        for (int nt = 0; nt < 8; nt++) {
            mx0 = fmaxf(mx0, fmaxf(sacc[mt][nt][0], sacc[mt][nt][1]));
            mx1 = fmaxf(mx1, fmaxf(sacc[mt][nt][2], sacc[mt][nt][3]));
        }
        mx0 = fmaxf(mx0, __shfl_xor_sync(~0u, mx0, 1));
        mx0 = fmaxf(mx0, __shfl_xor_sync(~0u, mx0, 2));
        mx1 = fmaxf(mx1, __shfl_xor_sync(~0u, mx1, 1));
        mx1 = fmaxf(mx1, __shfl_xor_sync(~0u, mx1, 2));
        mx0 *= scale; mx1 *= scale;

        float sum0 = 0.f, sum1 = 0.f;
        float e[8][4];
        #pragma unroll
        for (int nt = 0; nt < 8; nt++) {
            e[nt][0] = __expf(sacc[mt][nt][0] * scale - mx0);
            e[nt][1] = __expf(sacc[mt][nt][1] * scale - mx0);
            e[nt][2] = __expf(sacc[mt][nt][2] * scale - mx1);
            e[nt][3] = __expf(sacc[mt][nt][3] * scale - mx1);
            sum0 += e[nt][0] + e[nt][1];
            sum1 += e[nt][2] + e[nt][3];
        }
        sum0 += __shfl_xor_sync(~0u, sum0, 1);
        sum0 += __shfl_xor_sync(~0u, sum0, 2);
        sum1 += __shfl_xor_sync(~0u, sum1, 1);
        sum1 += __shfl_xor_sync(~0u, sum1, 2);
        float inv0 = 1.f / sum0, inv1 = 1.f / sum1;
        #pragma unroll
        for (int nt = 0; nt < 8; nt++) {
            p0[mt][nt] = pack2(e[nt][0] * inv0, e[nt][1] * inv0);
            p1[mt][nt] = pack2(e[nt][2] * inv1, e[nt][3] * inv1);
        }
    }

    // --- O = P @ V : V fragments via ldmatrix.trans, shared across m-tiles
    float oacc[2][6][4];
    #pragma unroll
    for (int mt = 0; mt < 2; mt++)
        #pragma unroll
        for (int nt = 0; nt < 6; nt++)
            #pragma unroll
            for (int j = 0; j < 4; j++) oacc[mt][nt][j] = 0.f;

    #pragma unroll
    for (int kc = 0; kc < 4; kc++) {
        #pragma unroll
        for (int j = 0; j < 3; j++) {
            uint32_t b[4];
            ldsm4t(b, sb + (uint32_t)((kc * 16 + vrow) * STRB
                                      + voffB + (2 * j + vsel) * 16));
            #pragma unroll
            for (int mt = 0; mt < 2; mt++) {
                uint32_t a0 = p0[mt][2 * kc],     a1 = p1[mt][2 * kc];
                uint32_t a2 = p0[mt][2 * kc + 1], a3 = p1[mt][2 * kc + 1];
                mma16(oacc[mt][2 * j],     a0, a1, a2, a3, b[0], b[1]);
                mma16(oacc[mt][2 * j + 1], a0, a1, a2, a3, b[2], b[3]);
            }
        }
    }

    #pragma unroll
    for (int mt = 0; mt < 2; mt++)
        #pragma unroll
        for (int nt = 0; nt < 6; nt++) {
            long col = head * 48 + nt * 8 + cg * 2;
            long r0 = tok0 + m0 + mt * 16 + gr;
            *(uint32_t*)(O + r0 * 384 + col)       = pack2(oacc[mt][nt][0], oacc[mt][nt][1]);
            *(uint32_t*)(O + (r0 + 8) * 384 + col) = pack2(oacc[mt][nt][2], oacc[mt][nt][3]);
        }
}

// ===========================================================================
// Kernel 5: LayerNorm2. fp16 in, fp16 out.
// ===========================================================================
__global__ void __launch_bounds__(128) ln2_kernel(
    const __half* __restrict__ Hh,
    const float* __restrict__ gw, const float* __restrict__ gb,
    __half* __restrict__ Y2)
{
    long t = blockIdx.x;
    int tid = threadIdx.x;
    const __half* row = Hh + t * 384;
    float v[3];
    float sum = 0.f, sq = 0.f;
    #pragma unroll
    for (int i = 0; i < 3; i++) {
        v[i] = __half2float(row[tid + i * 128]);
        sum += v[i]; sq += v[i] * v[i];
    }
    __shared__ float ssum[4], ssq[4];
    #pragma unroll
    for (int o = 16; o; o >>= 1) {
        sum += __shfl_xor_sync(~0u, sum, o);
        sq  += __shfl_xor_sync(~0u, sq,  o);
    }
    if ((tid & 31) == 0) { ssum[tid >> 5] = sum; ssq[tid >> 5] = sq; }
    __syncthreads();
    sum = ssum[0] + ssum[1] + ssum[2] + ssum[3];
    sq  = ssq[0]  + ssq[1]  + ssq[2]  + ssq[3];
    float m  = sum * (1.f / 384.f);
    float rs = rsqrtf(sq * (1.f / 384.f) - m * m + 1e-5f);
    #pragma unroll
    for (int i = 0; i < 3; i++) {
        int c = tid + i * 128;
        Y2[t * 384 + c] = __float2half((v[i] - m) * rs * gw[c] + gb[c]);
    }
}

// ===========================================================================
extern "C" void kernel_launch(void* const* d_in, const int* in_sizes, int n_in,
                              void* d_out, int out_size)
{
    const float* x     = (const float*)d_in[0];
    const float* n1_w  = (const float*)d_in[1];
    const float* n1_b  = (const float*)d_in[2];
    const float* in_w  = (const float*)d_in[3];
    const float* in_b  = (const float*)d_in[4];
    const float* out_w = (const float*)d_in[5];
    const float* out_b = (const float*)d_in[6];
    const float* n2_w  = (const float*)d_in[7];
    const float* n2_b  = (const float*)d_in[8];
    const float* w1    = (const float*)d_in[9];
    const float* b1    = (const float*)d_in[10];
    const float* w2    = (const float*)d_in[11];
    const float* b2    = (const float*)d_in[12];
    float* out = (float*)d_out;

    __half *WINh, *Yh, *Hb, *Wh;
    cudaGetSymbolAddress((void**)&WINh, g_hR);
    cudaGetSymbolAddress((void**)&Yh,   g_hA);
    cudaGetSymbolAddress((void**)&Hb,   g_hB);
    cudaGetSymbolAddress((void**)&Wh,   g_wh);

    __half* QKVh = Hb;
    __half* Oh   = Yh;
    __half* H    = WINh;
    __half* Y2h  = Hb;
    __half* Gh   = Hb + (size_t)TOKS * 384;

    cudaFuncSetAttribute((const void*)mma_gemm<0,384>, cudaFuncAttributeMaxDynamicSharedMemorySize, GEMM_SMEM);
    cudaFuncSetAttribute((const void*)mma_gemm<1,384>, cudaFuncAttributeMaxDynamicSharedMemorySize, GEMM_SMEM);
    cudaFuncSetAttribute((const void*)mma_gemm<2,384>, cudaFuncAttributeMaxDynamicSharedMemorySize, GEMM_SMEM);
    cudaFuncSetAttribute((const void*)mma_gemm<3,768>, cudaFuncAttributeMaxDynamicSharedMemorySize, GEMM_SMEM);
    cudaFuncSetAttribute((const void*)attn_kernel,     cudaFuncAttributeMaxDynamicSharedMemorySize, ATTN_SMEM);

    // 0. convert all weights to fp16
    cvt_all_kernel<<<4608, 256>>>(in_w, out_w, w1, w2, Wh);
    // 1. gather + LN1
    ln1_gather_kernel<<<2048 * 4, 256>>>(x, n1_w, n1_b, Yh, WINh);
    // 2. QKV projection
    mma_gemm<0,384><<<dim3(1152 / 128, TOKS / 128), 256, GEMM_SMEM>>>(Yh, Wh + WQKV_OFF, in_b, nullptr, QKVh, 1152);
    // 3. merged-window tensor-core attention
    attn_kernel<<<2048, 512, ATTN_SMEM>>>(QKVh, Oh);
    // 4. out projection + residual -> H
    mma_gemm<2,384><<<dim3(384 / 128, TOKS / 128), 256, GEMM_SMEM>>>(Oh, Wh + WO_OFF, out_b, WINh, H, 384);
    // 5. LN2
    ln2_kernel<<<TOKS, 128>>>(H, n2_w, n2_b, Y2h);
    // 6. MLP fc1 + gelu
    mma_gemm<1,384><<<dim3(768 / 128, TOKS / 128), 256, GEMM_SMEM>>>(Y2h, Wh + W1_OFF, b1, nullptr, Gh, 768);
    // 7. MLP fc2 + residual + window-reverse scatter
    mma_gemm<3,768><<<dim3(384 / 128, TOKS / 128), 256, GEMM_SMEM>>>(Gh, Wh + W2_OFF, b2, H, out, 384);
}

// round 10
// speedup vs baseline: 5.3199x; 1.0339x over previous
#include <cuda_runtime.h>
#include <cuda_fp16.h>
#include <math.h>
#include <stdint.h>

#define TOKS 131072          // 2048 windows * 64 tokens

// fp16 scratch
__device__ __half g_hR[(size_t)TOKS * 384];      // WIN, later H (residual, fp16)
__device__ __half g_hA[(size_t)TOKS * 384];      // Y (post-LN1), later O (attn out)
__device__ __half g_hB[(size_t)TOKS * 1152];     // QKV, later Y2 (384) + G (768)
__device__ __half g_wh[1179648];                 // weights converted to half

#define WQKV_OFF 0
#define WO_OFF   442368
#define W1_OFF   589824
#define W2_OFF   884736

#define GEMM_SMEM 65536

// ===========================================================================
// helpers
// ===========================================================================
__device__ __forceinline__ void cp16(uint32_t dst, const void* src) {
    asm volatile("cp.async.cg.shared.global [%0], [%1], 16;"
        :: "r"(dst), "l"(src));
}
__device__ __forceinline__ void mma16(float* d, uint32_t a0, uint32_t a1,
                                      uint32_t a2, uint32_t a3,
                                      uint32_t b0, uint32_t b1) {
    asm volatile(
        "mma.sync.aligned.m16n8k16.row.col.f32.f16.f16.f32 "
        "{%0,%1,%2,%3}, {%4,%5,%6,%7}, {%8,%9}, {%0,%1,%2,%3};"
        : "+f"(d[0]), "+f"(d[1]), "+f"(d[2]), "+f"(d[3])
        : "r"(a0), "r"(a1), "r"(a2), "r"(a3), "r"(b0), "r"(b1));
}
__device__ __forceinline__ void ldsm4(uint32_t* r, uint32_t addr) {
    asm volatile("ldmatrix.sync.aligned.m8n8.x4.shared.b16 {%0,%1,%2,%3}, [%4];"
        : "=r"(r[0]), "=r"(r[1]), "=r"(r[2]), "=r"(r[3]) : "r"(addr));
}
__device__ __forceinline__ void ldsm4t(uint32_t* r, uint32_t addr) {
    asm volatile("ldmatrix.sync.aligned.m8n8.x4.trans.shared.b16 {%0,%1,%2,%3}, [%4];"
        : "=r"(r[0]), "=r"(r[1]), "=r"(r[2]), "=r"(r[3]) : "r"(addr));
}
__device__ __forceinline__ uint32_t pack2(float a, float b) {
    __half2 h = __floats2half2_rn(a, b);
    return *(uint32_t*)&h;
}
__device__ __forceinline__ float2 unpack2(uint32_t u) {
    return __half22float2(*(__half2*)&u);
}

// ===========================================================================
// Kernel 0: all weights fp32 -> fp16 in one launch
// ===========================================================================
__global__ void __launch_bounds__(256) cvt_all_kernel(
    const float* __restrict__ a, const float* __restrict__ b,
    const float* __restrict__ c, const float* __restrict__ d,
    __half* __restrict__ o)
{
    int i = blockIdx.x * 256 + threadIdx.x;
    if (i < 442368)       o[i] = __float2half(a[i]);
    else if (i < 589824)  o[i] = __float2half(b[i - 442368]);
    else if (i < 884736)  o[i] = __float2half(c[i - 589824]);
    else if (i < 1179648) o[i] = __float2half(d[i - 884736]);
}

// ===========================================================================
// Kernel 1: window gather + LayerNorm1. WIN fp16, Y fp16.
// ===========================================================================
__global__ void __launch_bounds__(256) ln1_gather_kernel(
    const float* __restrict__ x,
    const float* __restrict__ gw, const float* __restrict__ gb,
    __half* __restrict__ Y, __half* __restrict__ WIN)
{
    __shared__ float tile[384][17];
    __shared__ float s_mu[16], s_rs[16];

    int blk  = blockIdx.x;
    int win  = blk >> 2;
    int part = blk & 3;
    int b  = win >> 8;
    int wh = (win >> 4) & 15;
    int ww = win & 15;

    int tid = threadIdx.x;
    int sl  = tid & 15;
    int s   = part * 16 + sl;
    int r   = s >> 3, cw = s & 7;
    long xbase = (long)b * 384 * 16384 + (long)(wh * 8 + r) * 128 + ww * 8 + cw;

    for (int c = tid >> 4; c < 384; c += 16)
        tile[c][sl] = x[xbase + (long)c * 16384];
    __syncthreads();

    int lane = tid & 31, wd = tid >> 5;
    for (int t = wd * 2; t < wd * 2 + 2; t++) {
        float sum = 0.f, sq = 0.f;
        for (int c = lane; c < 384; c += 32) {
            float v = tile[c][t];
            sum += v; sq += v * v;
        }
        #pragma unroll
        for (int o = 16; o; o >>= 1) {
            sum += __shfl_xor_sync(~0u, sum, o);
            sq  += __shfl_xor_sync(~0u, sq,  o);
        }
        if (lane == 0) {
            float m = sum * (1.f / 384.f);
            float var = sq * (1.f / 384.f) - m * m;
            s_mu[t] = m;
            s_rs[t] = rsqrtf(var + 1e-5f);
        }
    }
    __syncthreads();

    long tok0 = (long)win * 64 + part * 16;
    for (int idx = tid; idx < 16 * 384; idx += 256) {
        int c = idx % 384, t = idx / 384;
        float v = tile[c][t];
        long o = (tok0 + t) * 384 + c;
        WIN[o] = __float2half(v);
        Y[o] = __float2half((v - s_mu[t]) * s_rs[t] * gw[c] + gb[c]);
    }
}

// ===========================================================================
// FP16 tensor-core GEMM, compile-time K. BM=128, BN=128, BK=32, 4-stage
// cp.async, 256 threads, ldmatrix + swizzle. Fully unrolled mainloop.
// ===========================================================================
template<int MODE, int K>
__global__ void __launch_bounds__(256, 2) mma_gemm(
    const __half* __restrict__ A, const __half* __restrict__ W,
    const float* __restrict__ bias, const __half* __restrict__ res,
    void* __restrict__ outp, int N)
{
    extern __shared__ uint32_t sm[];

    const int tid  = threadIdx.x;
    const int lane = tid & 31, wid = tid >> 5;
    const int wm = wid & 1;
    const int wn = wid >> 1;
    const int gr = lane >> 2;
    const int cg = lane & 3;

    const long m0 = (long)blockIdx.y * 128;
    const int  n0 = blockIdx.x * 128;

    const uint32_t sb = (uint32_t)__cvta_generic_to_shared(sm);
    const __half* Ag = A + m0 * K;
    const __half* Wg = W + (long)n0 * K;

    float acc[4][4][4];
    #pragma unroll
    for (int i = 0; i < 4; i++)
        #pragma unroll
        for (int j = 0; j < 4; j++)
            #pragma unroll
            for (int k = 0; k < 4; k++) acc[i][j][k] = 0.f;

    constexpr int NS = K >> 5;

    auto issue = [&](int s, int p) {
        #pragma unroll
        for (int i = 0; i < 2; i++) {
            int idx = tid + i * 256;
            int row = idx >> 2, c = idx & 3;
            int line = row >> 1;
            uint32_t u = (uint32_t)((((row & 1) << 2) + c) ^ (line & 7));
            uint32_t off = p * 16384u + line * 128u + u * 16u;
            cp16(sb + off,          Ag + (long)row * K + s * 32 + c * 8);
            cp16(sb + 8192u + off,  Wg + (long)row * K + s * 32 + c * 8);
        }
        asm volatile("cp.async.commit_group;");
    };

    const int lrow = (lane & 7) + ((lane >> 3) & 1) * 8;
    const int lk   = lane >> 4;

    issue(0, 0);
    issue(1, 1);
    issue(2, 2);
    #pragma unroll
    for (int s = 0; s < NS; s++) {
        const int p = s & 3;
        if (s + 2 < NS)      asm volatile("cp.async.wait_group 2;");
        else if (s + 1 < NS) asm volatile("cp.async.wait_group 1;");
        else                 asm volatile("cp.async.wait_group 0;");
        __syncthreads();
        if (s + 3 < NS) issue(s + 3, (s + 3) & 3);

        const uint32_t abase = sb + p * 16384u;
        const uint32_t bbase = abase + 8192u;

        #pragma unroll
        for (int kc = 0; kc < 2; kc++) {
            int c = kc * 2 + lk;
            uint32_t af[4][4], bq[2][4];
            #pragma unroll
            for (int mt = 0; mt < 4; mt++) {
                int row = wm * 64 + mt * 16 + lrow;
                int line = row >> 1;
                uint32_t u = (uint32_t)((((row & 1) << 2) + c) ^ (line & 7));
                ldsm4(af[mt], abase + line * 128u + u * 16u);
            }
            #pragma unroll
            for (int pr = 0; pr < 2; pr++) {
                int row = wn * 32 + pr * 16 + lrow;
                int line = row >> 1;
                uint32_t u = (uint32_t)((((row & 1) << 2) + c) ^ (line & 7));
                ldsm4(bq[pr], bbase + line * 128u + u * 16u);
            }
            #pragma unroll
            for (int mt = 0; mt < 4; mt++)
                #pragma unroll
                for (int nt = 0; nt < 4; nt++) {
                    int pr = nt >> 1, hi = nt & 1;
                    mma16(acc[mt][nt], af[mt][0], af[mt][1], af[mt][2], af[mt][3],
                          bq[pr][hi], bq[pr][hi + 2]);
                }
        }
    }

    if (MODE != 3) {
        #pragma unroll
        for (int mt = 0; mt < 4; mt++) {
            #pragma unroll
            for (int nt = 0; nt < 4; nt++) {
                int n = n0 + wn * 32 + nt * 8 + cg * 2;
                float2 b2 = *(const float2*)(bias + n);
                #pragma unroll
                for (int h = 0; h < 2; h++) {
                    long r = m0 + wm * 64 + mt * 16 + h * 8 + gr;
                    float v0 = acc[mt][nt][h * 2 + 0] + b2.x;
                    float v1 = acc[mt][nt][h * 2 + 1] + b2.y;
                    if (MODE == 1) {
                        v0 = 0.5f * v0 * (1.f + erff(v0 * 0.70710678118654752f));
                        v1 = 0.5f * v1 * (1.f + erff(v1 * 0.70710678118654752f));
                    }
                    if (MODE == 2) {
                        float2 rr = unpack2(*(const uint32_t*)(res + r * N + n));
                        v0 += rr.x; v1 += rr.y;
                    }
                    *(uint32_t*)((__half*)outp + r * N + n) = pack2(v0, v1);
                }
            }
        }
    } else {
        float* out = (float*)outp;
        __syncthreads();
        float* T = (float*)sm;    // [128][66] floats
        #pragma unroll
        for (int chunk = 0; chunk < 2; chunk++) {
            if ((wn >> 1) == chunk) {
                #pragma unroll
                for (int mt = 0; mt < 4; mt++) {
                    #pragma unroll
                    for (int nt = 0; nt < 4; nt++) {
                        int cl = (wn & 1) * 32 + nt * 8 + cg * 2;
                        int n  = n0 + chunk * 64 + cl;
                        float2 b2 = *(const float2*)(bias + n);
                        #pragma unroll
                        for (int h = 0; h < 2; h++) {
                            int rl = wm * 64 + mt * 16 + h * 8 + gr;
                            long r = m0 + rl;
                            float2 rr = unpack2(*(const uint32_t*)(res + r * 384 + n));
                            T[rl * 66 + cl]     = acc[mt][nt][h * 2 + 0] + b2.x + rr.x;
                            T[rl * 66 + cl + 1] = acc[mt][nt][h * 2 + 1] + b2.y + rr.y;
                        }
                    }
                }
            }
            __syncthreads();
            int ch = tid & 63;
            for (int g = tid >> 6; g < 16; g += 4) {
                long m = m0 + g * 8;
                int winI = (int)(m >> 6), sI = (int)(m & 63);
                int bI = winI >> 8, whI = (winI >> 4) & 15, wwI = winI & 15;
                int n = n0 + chunk * 64 + ch;
                long base = ((long)(bI * 384 + n)) * 16384
                          + (long)(whI * 8 + (sI >> 3)) * 128 + wwI * 8;
                float v[8];
                #pragma unroll
                for (int i = 0; i < 8; i++) v[i] = T[(g * 8 + i) * 66 + ch];
                *(float4*)(out + base)     = make_float4(v[0], v[1], v[2], v[3]);
                *(float4*)(out + base + 4) = make_float4(v[4], v[5], v[6], v[7]);
            }
            __syncthreads();
        }
    }
}

// ===========================================================================
// Kernel 3: tensor-core attention. One block = 2 heads of one window.
// 256 threads = 8 warps: warp (hl, q) -> head h0+hl, rows q*16..q*16+15.
// smem: 64 rows x 296 halves ([Q2|K2|V2] packed, 592B stride = 37 odd 16B
// units -> conflict-free ldmatrix). 37888 B -> 4 CTAs/SM; one m16 tile per
// warp keeps regs <= 64 (launch_bounds(256,4)).
// ===========================================================================
__global__ void __launch_bounds__(256, 4) attn_kernel(
    const __half* __restrict__ QKV, __half* __restrict__ O)
{
    __shared__ __half qkv[64 * 296];
    const int STRB = 592;             // row stride in bytes

    const int hp  = blockIdx.x;       // head pair 0..3
    const int h0  = hp * 2;
    const long tok0 = (long)blockIdx.y * 64;
    const int tid = threadIdx.x;
    const int lane = tid & 31, wid = tid >> 5;

    // stage Q|K|V slices for 2 heads: 64 rows x 36 16B-chunks
    // head h0's slice within each Q/K/V part starts at column h0*48
    const __half* g = QKV + tok0 * 1152 + h0 * 48;
    #pragma unroll
    for (int i = 0; i < 9; i++) {
        int ch = tid + i * 256;
        int row = ch / 36, seg = ch % 36;
        int part = seg / 12, sub = seg % 12;
        *(uint4*)&qkv[row * 296 + seg * 8] =
            *(const uint4*)(g + (long)row * 1152 + part * 384 + sub * 8);
    }
    __syncthreads();

    const uint32_t sb = (uint32_t)__cvta_generic_to_shared(qkv);
    const int hl = wid >> 2;          // head local 0/1
    const int m0 = (wid & 3) * 16;    // row tile
    const int gr = lane >> 2, cg = lane & 3;

    const int qoffB = hl * 96;        // bytes
    const int koffB = 192 + hl * 96;
    const int voffB = 384 + hl * 96;

    const int lrow = (lane & 7) + ((lane >> 3) & 1) * 8;   // A rows
    const int lkA  = lane >> 4;                            // A col half
    const int krow = (lane & 7) + ((lane >> 4) & 1) * 8;   // K rows
    const int kcolb= ((lane >> 3) & 1) * 16;
    const int vrow = (lane & 7) + ((lane >> 3) & 1) * 8;   // V rows
    const int vsel = lane >> 4;

    // --- S = Q K^T : 1 m-tile x 8 n-tiles
    float sacc[8][4];
    #pragma unroll
    for (int nt = 0; nt < 8; nt++)
        #pragma unroll
        for (int j = 0; j < 4; j++) sacc[nt][j] = 0.f;

    #pragma unroll
    for (int kc = 0; kc < 3; kc++) {
        uint32_t a[4];
        ldsm4(a, sb + (uint32_t)((m0 + lrow) * STRB + qoffB + kc * 32 + lkA * 16));
        #pragma unroll
        for (int j = 0; j < 4; j++) {
            uint32_t b[4];
            ldsm4(b, sb + (uint32_t)((j * 16 + krow) * STRB + koffB + kc * 32 + kcolb));
            mma16(sacc[2 * j],     a[0], a[1], a[2], a[3], b[0], b[1]);
            mma16(sacc[2 * j + 1], a[0], a[1], a[2], a[3], b[2], b[3]);
        }
    }

    // --- register softmax (rows gr and gr+8), scale = 1/sqrt(48)
    const float scale = 0.14433756729740645f;
    float mx0 = -1e30f, mx1 = -1e30f;
    #pragma unroll
    for (int nt = 0; nt < 8; nt++) {
        mx0 = fmaxf(mx0, fmaxf(sacc[nt][0], sacc[nt][1]));
        mx1 = fmaxf(mx1, fmaxf(sacc[nt][2], sacc[nt][3]));
    }
    mx0 = fmaxf(mx0, __shfl_xor_sync(~0u, mx0, 1));
    mx0 = fmaxf(mx0, __shfl_xor_sync(~0u, mx0, 2));
    mx1 = fmaxf(mx1, __shfl_xor_sync(~0u, mx1, 1));
    mx1 = fmaxf(mx1, __shfl_xor_sync(~0u, mx1, 2));
    mx0 *= scale; mx1 *= scale;

    float e[8][4];
    float sum0 = 0.f, sum1 = 0.f;
    #pragma unroll
    for (int nt = 0; nt < 8; nt++) {
        e[nt][0] = __expf(sacc[nt][0] * scale - mx0);
        e[nt][1] = __expf(sacc[nt][1] * scale - mx0);
        e[nt][2] = __expf(sacc[nt][2] * scale - mx1);
        e[nt][3] = __expf(sacc[nt][3] * scale - mx1);
        sum0 += e[nt][0] + e[nt][1];
        sum1 += e[nt][2] + e[nt][3];
    }
    sum0 += __shfl_xor_sync(~0u, sum0, 1);
    sum0 += __shfl_xor_sync(~0u, sum0, 2);
    sum1 += __shfl_xor_sync(~0u, sum1, 1);
    sum1 += __shfl_xor_sync(~0u, sum1, 2);
    float inv0 = 1.f / sum0, inv1 = 1.f / sum1;

    uint32_t p0[8], p1[8];
    #pragma unroll
    for (int nt = 0; nt < 8; nt++) {
        p0[nt] = pack2(e[nt][0] * inv0, e[nt][1] * inv0);
        p1[nt] = pack2(e[nt][2] * inv1, e[nt][3] * inv1);
    }

    // --- O = P @ V : V fragments via ldmatrix.trans
    float oacc[6][4];
    #pragma unroll
    for (int nt = 0; nt < 6; nt++)
        #pragma unroll
        for (int j = 0; j < 4; j++) oacc[nt][j] = 0.f;

    #pragma unroll
    for (int kc = 0; kc < 4; kc++) {
        uint32_t a0 = p0[2 * kc],     a1 = p1[2 * kc];
        uint32_t a2 = p0[2 * kc + 1], a3 = p1[2 * kc + 1];
        #pragma unroll
        for (int j = 0; j < 3; j++) {
            uint32_t b[4];
            ldsm4t(b, sb + (uint32_t)((kc * 16 + vrow) * STRB
                                      + voffB + (2 * j + vsel) * 16));
            mma16(oacc[2 * j],     a0, a1, a2, a3, b[0], b[1]);
            mma16(oacc[2 * j + 1], a0, a1, a2, a3, b[2], b[3]);
        }
    }

    #pragma unroll
    for (int nt = 0; nt < 6; nt++) {
        long col = (h0 + hl) * 48 + nt * 8 + cg * 2;
        long r0 = tok0 + m0 + gr;
        *(uint32_t*)(O + r0 * 384 + col)       = pack2(oacc[nt][0], oacc[nt][1]);
        *(uint32_t*)(O + (r0 + 8) * 384 + col) = pack2(oacc[nt][2], oacc[nt][3]);
    }
}

// ===========================================================================
// Kernel 5: LayerNorm2, vectorized. 384 threads = 4 tokens x 96 threads;
// each thread handles 4 halves (uint2). fp16 in/out.
// ===========================================================================
__global__ void __launch_bounds__(384) ln2_kernel(
    const __half* __restrict__ Hh,
    const float* __restrict__ gw, const float* __restrict__ gb,
    __half* __restrict__ Y2)
{
    __shared__ float ssum[12], ssq[12];

    int tid = threadIdx.x;
    int tk = tid / 96;            // token in block 0..3
    int tl = tid % 96;            // lane within token
    long t = (long)blockIdx.x * 4 + tk;

    uint2 u = *(const uint2*)(Hh + t * 384 + tl * 4);
    float2 v01 = unpack2(u.x), v23 = unpack2(u.y);
    float sum = v01.x + v01.y + v23.x + v23.y;
    float sq  = v01.x * v01.x + v01.y * v01.y + v23.x * v23.x + v23.y * v23.y;

    #pragma unroll
    for (int o = 16; o; o >>= 1) {
        sum += __shfl_xor_sync(~0u, sum, o);
        sq  += __shfl_xor_sync(~0u, sq,  o);
    }
    int wrp = tid >> 5;           // 0..11, 3 warps per token
    if ((tid & 31) == 0) { ssum[wrp] = sum; ssq[wrp] = sq; }
    __syncthreads();
    sum = ssum[tk * 3] + ssum[tk * 3 + 1] + ssum[tk * 3 + 2];
    sq  = ssq[tk * 3]  + ssq[tk * 3 + 1]  + ssq[tk * 3 + 2];

    float m  = sum * (1.f / 384.f);
    float rs = rsqrtf(sq * (1.f / 384.f) - m * m + 1e-5f);

    int c = tl * 4;
    float4 w4 = *(const float4*)(gw + c);
    float4 b4 = *(const float4*)(gb + c);
    uint2 o;
    o.x = pack2((v01.x - m) * rs * w4.x + b4.x, (v01.y - m) * rs * w4.y + b4.y);
    o.y = pack2((v23.x - m) * rs * w4.z + b4.z, (v23.y - m) * rs * w4.w + b4.w);
    *(uint2*)(Y2 + t * 384 + c) = o;
}

// ===========================================================================
extern "C" void kernel_launch(void* const* d_in, const int* in_sizes, int n_in,
                              void* d_out, int out_size)
{
    const float* x     = (const float*)d_in[0];
    const float* n1_w  = (const float*)d_in[1];
    const float* n1_b  = (const float*)d_in[2];
    const float* in_w  = (const float*)d_in[3];
    const float* in_b  = (const float*)d_in[4];
    const float* out_w = (const float*)d_in[5];
    const float* out_b = (const float*)d_in[6];
    const float* n2_w  = (const float*)d_in[7];
    const float* n2_b  = (const float*)d_in[8];
    const float* w1    = (const float*)d_in[9];
    const float* b1    = (const float*)d_in[10];
    const float* w2    = (const float*)d_in[11];
    const float* b2    = (const float*)d_in[12];
    float* out = (float*)d_out;

    __half *WINh, *Yh, *Hb, *Wh;
    cudaGetSymbolAddress((void**)&WINh, g_hR);
    cudaGetSymbolAddress((void**)&Yh,   g_hA);
    cudaGetSymbolAddress((void**)&Hb,   g_hB);
    cudaGetSymbolAddress((void**)&Wh,   g_wh);

    __half* QKVh = Hb;
    __half* Oh   = Yh;
    __half* H    = WINh;
    __half* Y2h  = Hb;
    __half* Gh   = Hb + (size_t)TOKS * 384;

    cudaFuncSetAttribute((const void*)mma_gemm<0,384>, cudaFuncAttributeMaxDynamicSharedMemorySize, GEMM_SMEM);
    cudaFuncSetAttribute((const void*)mma_gemm<1,384>, cudaFuncAttributeMaxDynamicSharedMemorySize, GEMM_SMEM);
    cudaFuncSetAttribute((const void*)mma_gemm<2,384>, cudaFuncAttributeMaxDynamicSharedMemorySize, GEMM_SMEM);
    cudaFuncSetAttribute((const void*)mma_gemm<3,768>, cudaFuncAttributeMaxDynamicSharedMemorySize, GEMM_SMEM);

    // 0. convert all weights to fp16
    cvt_all_kernel<<<4608, 256>>>(in_w, out_w, w1, w2, Wh);
    // 1. gather + LN1
    ln1_gather_kernel<<<2048 * 4, 256>>>(x, n1_w, n1_b, Yh, WINh);
    // 2. QKV projection
    mma_gemm<0,384><<<dim3(1152 / 128, TOKS / 128), 256, GEMM_SMEM>>>(Yh, Wh + WQKV_OFF, in_b, nullptr, QKVh, 1152);
    // 3. tensor-core attention: 2 heads per block, 4 CTAs/SM
    attn_kernel<<<dim3(4, 2048), 256>>>(QKVh, Oh);
    // 4. out projection + residual -> H
    mma_gemm<2,384><<<dim3(384 / 128, TOKS / 128), 256, GEMM_SMEM>>>(Oh, Wh + WO_OFF, out_b, WINh, H, 384);
    // 5. LN2 (vectorized, 4 tokens/block)
    ln2_kernel<<<TOKS / 4, 384>>>(H, n2_w, n2_b, Y2h);
    // 6. MLP fc1 + gelu
    mma_gemm<1,384><<<dim3(768 / 128, TOKS / 128), 256, GEMM_SMEM>>>(Y2h, Wh + W1_OFF, b1, nullptr, Gh, 768);
    // 7. MLP fc2 + residual + window-reverse scatter
    mma_gemm<3,768><<<dim3(384 / 128, TOKS / 128), 256, GEMM_SMEM>>>(Gh, Wh + W2_OFF, b2, H, out, 384);
}